// round 2
// baseline (speedup 1.0000x reference)
#include <cuda_runtime.h>
#include <math.h>
#include <stdint.h>

// Problem constants
#define BB    4
#define TSEQ  2048
#define CDIM  768
#define HEADS 12
#define HD    64
#define MLPD  3072
#define NTOK  (BB*TSEQ)          // 8192

// ---------------------------------------------------------------------------
// Scratch (device globals; no allocation allowed)
// ---------------------------------------------------------------------------
__device__ float g_xn [NTOK*CDIM];
__device__ float g_q  [NTOK*CDIM];
__device__ float g_k  [NTOK*CDIM];
__device__ float g_v  [NTOK*CDIM];
__device__ float g_att[NTOK*CDIM];
__device__ float g_x2 [NTOK*CDIM];
__device__ float g_y  [NTOK*CDIM];
__device__ float g_h  [NTOK*MLPD];
__device__ float g_wq [CDIM*HEADS*HD];
__device__ float g_wk [CDIM*HEADS*HD];
__device__ float g_wv [CDIM*HEADS*HD];

// ---------------------------------------------------------------------------
// Repack [H,C,D] -> [C, H*D] for Q/K/V weights
// ---------------------------------------------------------------------------
__global__ void repack3_kernel(const float* __restrict__ wq,
                               const float* __restrict__ wk,
                               const float* __restrict__ wv,
                               float* __restrict__ oq,
                               float* __restrict__ ok,
                               float* __restrict__ ov) {
    int i = blockIdx.x * 256 + threadIdx.x;
    if (i >= HEADS * CDIM * HD) return;
    int h = i / (CDIM * HD);
    int r = i % (CDIM * HD);
    int c = r / HD;
    int d = r % HD;
    int o = c * (HEADS * HD) + h * HD + d;
    oq[o] = wq[i];
    ok[o] = wk[i];
    ov[o] = wv[i];
}

// ---------------------------------------------------------------------------
// LayerNorm: one block per token row, 256 threads, C=768 -> 3 elems/thread
// ---------------------------------------------------------------------------
__global__ void ln_kernel(const float* __restrict__ x,
                          const float* __restrict__ g,
                          const float* __restrict__ b,
                          float* __restrict__ out) {
    int row = blockIdx.x;
    int tid = threadIdx.x;
    const float* xr = x + (size_t)row * CDIM;

    float v0 = xr[tid];
    float v1 = xr[tid + 256];
    float v2 = xr[tid + 512];
    float s  = v0 + v1 + v2;
    float s2 = v0*v0 + v1*v1 + v2*v2;

    #pragma unroll
    for (int o = 16; o > 0; o >>= 1) {
        s  += __shfl_xor_sync(0xffffffffu, s,  o);
        s2 += __shfl_xor_sync(0xffffffffu, s2, o);
    }
    __shared__ float rs[8], rs2[8];
    int w = tid >> 5, l = tid & 31;
    if (l == 0) { rs[w] = s; rs2[w] = s2; }
    __syncthreads();
    if (tid < 32) {
        float a  = (l < 8) ? rs[l]  : 0.f;
        float a2 = (l < 8) ? rs2[l] : 0.f;
        #pragma unroll
        for (int o = 4; o > 0; o >>= 1) {
            a  += __shfl_xor_sync(0xffffffffu, a,  o);
            a2 += __shfl_xor_sync(0xffffffffu, a2, o);
        }
        if (l == 0) { rs[0] = a; rs2[0] = a2; }
    }
    __syncthreads();
    float mu  = rs[0] * (1.f / CDIM);
    float var = rs2[0] * (1.f / CDIM) - mu * mu;
    float inv = rsqrtf(var + 1e-6f);

    float* orow = out + (size_t)row * CDIM;
    orow[tid]       = (v0 - mu) * inv * g[tid]       + b[tid];
    orow[tid + 256] = (v1 - mu) * inv * g[tid + 256] + b[tid + 256];
    orow[tid + 512] = (v2 - mu) * inv * g[tid + 512] + b[tid + 512];
}

// ---------------------------------------------------------------------------
// SGEMM: C = act(A[M,K] @ B[K,N] + bias) + res
// 128x128 tile, BK=8, 256 threads, 8x8 per thread. All dims multiples of 128/8.
// ACT: 0=none, 1=exact GELU
// ---------------------------------------------------------------------------
__device__ __forceinline__ float gelu_exact(float v) {
    return 0.5f * v * (1.0f + erff(v * 0.70710678118654752f));
}

template<int ACT, int HASBIAS, int HASRES>
__global__ void __launch_bounds__(256, 2)
sgemm_kernel(const float* __restrict__ A, const float* __restrict__ B,
             const float* __restrict__ bias, const float* __restrict__ res,
             float* __restrict__ C, int M, int N, int K) {
    __shared__ float As[8 * 128];   // As[k][m]
    __shared__ float Bs[8 * 128];   // Bs[k][n]

    int tid = threadIdx.x;
    int tx = tid & 15, ty = tid >> 4;
    int m0 = blockIdx.y * 128, n0 = blockIdx.x * 128;

    float acc[8][8];
    #pragma unroll
    for (int r = 0; r < 8; r++)
        #pragma unroll
        for (int c = 0; c < 8; c++) acc[r][c] = 0.f;

    int arow = tid >> 1;          // 0..127
    int ak   = (tid & 1) * 4;     // 0 or 4
    int brow = tid >> 5;          // 0..7
    int bcol = (tid & 31) * 4;    // 0..124

    const float* Aptr = A + (size_t)(m0 + arow) * K + ak;

    for (int k0 = 0; k0 < K; k0 += 8) {
        float4 a4 = *(const float4*)(Aptr + k0);
        float4 b4 = *(const float4*)(B + (size_t)(k0 + brow) * N + n0 + bcol);
        __syncthreads();
        As[(ak + 0) * 128 + arow] = a4.x;
        As[(ak + 1) * 128 + arow] = a4.y;
        As[(ak + 2) * 128 + arow] = a4.z;
        As[(ak + 3) * 128 + arow] = a4.w;
        *(float4*)&Bs[brow * 128 + bcol] = b4;
        __syncthreads();

        #pragma unroll
        for (int kk = 0; kk < 8; kk++) {
            float4 a0 = *(float4*)&As[kk * 128 + ty * 8];
            float4 a1 = *(float4*)&As[kk * 128 + ty * 8 + 4];
            float4 b0 = *(float4*)&Bs[kk * 128 + tx * 8];
            float4 b1 = *(float4*)&Bs[kk * 128 + tx * 8 + 4];
            float ar[8] = {a0.x, a0.y, a0.z, a0.w, a1.x, a1.y, a1.z, a1.w};
            float br[8] = {b0.x, b0.y, b0.z, b0.w, b1.x, b1.y, b1.z, b1.w};
            #pragma unroll
            for (int r = 0; r < 8; r++)
                #pragma unroll
                for (int c = 0; c < 8; c++)
                    acc[r][c] += ar[r] * br[c];
        }
    }

    // Epilogue
    #pragma unroll
    for (int r = 0; r < 8; r++) {
        int gr = m0 + ty * 8 + r;
        #pragma unroll
        for (int cs = 0; cs < 2; cs++) {
            int gc = n0 + tx * 8 + cs * 4;
            float4 v;
            v.x = acc[r][cs * 4 + 0];
            v.y = acc[r][cs * 4 + 1];
            v.z = acc[r][cs * 4 + 2];
            v.w = acc[r][cs * 4 + 3];
            if (HASBIAS) {
                float4 bb4 = *(const float4*)&bias[gc];
                v.x += bb4.x; v.y += bb4.y; v.z += bb4.z; v.w += bb4.w;
            }
            if (ACT == 1) {
                v.x = gelu_exact(v.x); v.y = gelu_exact(v.y);
                v.z = gelu_exact(v.z); v.w = gelu_exact(v.w);
            }
            if (HASRES) {
                float4 r4 = *(const float4*)&res[(size_t)gr * N + gc];
                v.x += r4.x; v.y += r4.y; v.z += r4.z; v.w += r4.w;
            }
            *(float4*)&C[(size_t)gr * N + gc] = v;
        }
    }
}

// ---------------------------------------------------------------------------
// Flash attention (no mask): per (b,h), BR=64 query rows/block, BC=32 kv tile.
// Layouts: Q/K/V/O are [b, t, h*64+d] row-major (stride CDIM).
// ---------------------------------------------------------------------------
__global__ void __launch_bounds__(256, 4)
flash_kernel(const float* __restrict__ Q, const float* __restrict__ K,
             const float* __restrict__ V, float* __restrict__ O) {
    __shared__ float sq [64 * 64];   // q tile  [r][d], stride 64
    __shared__ float skp[32 * 68];   // k tile  [s][d] stride 68 ; later p [r][j] stride 32
    __shared__ float sv [32 * 68];   // v tile  [s][d], stride 68

    int tid = threadIdx.x;
    int tx = tid & 15, ty = tid >> 4;
    int bh = blockIdx.y;
    int b = bh / HEADS, h = bh % HEADS;
    int t0 = blockIdx.x * 64;
    size_t base = (size_t)b * TSEQ * CDIM + (size_t)h * HD;

    // load q tile (64 x 64)
    #pragma unroll
    for (int it = 0; it < 4; it++) {
        int vi = tid + 256 * it;
        int r = vi >> 4;
        int cq = (vi & 15) * 4;
        *(float4*)&sq[r * 64 + cq] =
            *(const float4*)&Q[base + (size_t)(t0 + r) * CDIM + cq];
    }

    float acc[4][4];
    float rm[4], rl[4];
    #pragma unroll
    for (int r = 0; r < 4; r++) {
        rm[r] = -1e30f; rl[r] = 0.f;
        #pragma unroll
        for (int c = 0; c < 4; c++) acc[r][c] = 0.f;
    }
    const float scale = 0.03608439182435161f;   // 768^-0.5

    for (int kt = 0; kt < TSEQ / 32; kt++) {
        int s0 = kt * 32;
        __syncthreads();   // prior-iteration p/v reads done
        #pragma unroll
        for (int it = 0; it < 2; it++) {
            int vi = tid + 256 * it;
            int r = vi >> 4;
            int cq = (vi & 15) * 4;
            size_t goff = base + (size_t)(s0 + r) * CDIM + cq;
            *(float4*)&skp[r * 68 + cq] = *(const float4*)&K[goff];
            *(float4*)&sv [r * 68 + cq] = *(const float4*)&V[goff];
        }
        __syncthreads();

        // S = Q K^T : thread covers rows 4*ty..+3, cols 2*tx..+1
        float sacc[4][2];
        #pragma unroll
        for (int r = 0; r < 4; r++) { sacc[r][0] = 0.f; sacc[r][1] = 0.f; }
        #pragma unroll
        for (int d = 0; d < 64; d += 4) {
            float4 qa[4], kb[2];
            #pragma unroll
            for (int r = 0; r < 4; r++) qa[r] = *(float4*)&sq[(ty * 4 + r) * 64 + d];
            #pragma unroll
            for (int c = 0; c < 2; c++) kb[c] = *(float4*)&skp[(tx * 2 + c) * 68 + d];
            #pragma unroll
            for (int r = 0; r < 4; r++) {
                #pragma unroll
                for (int c = 0; c < 2; c++) {
                    sacc[r][c] += qa[r].x * kb[c].x + qa[r].y * kb[c].y
                                + qa[r].z * kb[c].z + qa[r].w * kb[c].w;
                }
            }
        }

        // online softmax stats (per row; reduce over 16 tx lanes = half-warp)
        float p[4][2];
        #pragma unroll
        for (int r = 0; r < 4; r++) {
            float srow0 = sacc[r][0] * scale;
            float srow1 = sacc[r][1] * scale;
            float mx = fmaxf(srow0, srow1);
            #pragma unroll
            for (int o = 8; o > 0; o >>= 1)
                mx = fmaxf(mx, __shfl_xor_sync(0xffffffffu, mx, o));
            float mnew = fmaxf(rm[r], mx);
            float alpha = __expf(rm[r] - mnew);
            p[r][0] = __expf(srow0 - mnew);
            p[r][1] = __expf(srow1 - mnew);
            float sm = p[r][0] + p[r][1];
            #pragma unroll
            for (int o = 8; o > 0; o >>= 1)
                sm += __shfl_xor_sync(0xffffffffu, sm, o);
            rl[r] = rl[r] * alpha + sm;
            rm[r] = mnew;
            #pragma unroll
            for (int c = 0; c < 4; c++) acc[r][c] *= alpha;
        }

        __syncthreads();   // all K reads done; safe to overwrite skp with P
        #pragma unroll
        for (int r = 0; r < 4; r++) {
            skp[(ty * 4 + r) * 32 + tx * 2 + 0] = p[r][0];
            skp[(ty * 4 + r) * 32 + tx * 2 + 1] = p[r][1];
        }
        __syncthreads();

        // O += P V : thread covers rows 4*ty..+3, d cols 4*tx..+3
        #pragma unroll
        for (int j = 0; j < 32; j += 4) {
            float4 pr[4];
            float vvf[4][4];
            #pragma unroll
            for (int r = 0; r < 4; r++)
                pr[r] = *(float4*)&skp[(ty * 4 + r) * 32 + j];
            #pragma unroll
            for (int jj = 0; jj < 4; jj++) {
                float4 t = *(float4*)&sv[(j + jj) * 68 + tx * 4];
                vvf[jj][0] = t.x; vvf[jj][1] = t.y; vvf[jj][2] = t.z; vvf[jj][3] = t.w;
            }
            #pragma unroll
            for (int r = 0; r < 4; r++) {
                #pragma unroll
                for (int c = 0; c < 4; c++) {
                    acc[r][c] += pr[r].x * vvf[0][c] + pr[r].y * vvf[1][c]
                               + pr[r].z * vvf[2][c] + pr[r].w * vvf[3][c];
                }
            }
        }
    }

    // epilogue: O = acc / l
    #pragma unroll
    for (int r = 0; r < 4; r++) {
        float inv = 1.f / rl[r];
        int row = t0 + ty * 4 + r;
        float4 o4;
        o4.x = acc[r][0] * inv;
        o4.y = acc[r][1] * inv;
        o4.z = acc[r][2] * inv;
        o4.w = acc[r][3] * inv;
        *(float4*)&O[base + (size_t)row * CDIM + tx * 4] = o4;
    }
}

// ---------------------------------------------------------------------------
// Launch
// ---------------------------------------------------------------------------
extern "C" void kernel_launch(void* const* d_in, const int* in_sizes, int n_in,
                              void* d_out, int out_size) {
    const float* x     = (const float*)d_in[0];
    const float* Wq    = (const float*)d_in[1];
    const float* Wk    = (const float*)d_in[2];
    const float* Wv    = (const float*)d_in[3];
    const float* Wo    = (const float*)d_in[4];
    const float* bo    = (const float*)d_in[5];
    const float* ln1_g = (const float*)d_in[6];
    const float* ln1_b = (const float*)d_in[7];
    const float* ln2_g = (const float*)d_in[8];
    const float* ln2_b = (const float*)d_in[9];
    const float* W1    = (const float*)d_in[10];
    const float* b1    = (const float*)d_in[11];
    const float* W2    = (const float*)d_in[12];
    const float* b2    = (const float*)d_in[13];
    float* out = (float*)d_out;

    float *xn, *q, *k, *v, *att, *x2, *y, *hbuf, *wq, *wk, *wv;
    cudaGetSymbolAddress((void**)&xn,  g_xn);
    cudaGetSymbolAddress((void**)&q,   g_q);
    cudaGetSymbolAddress((void**)&k,   g_k);
    cudaGetSymbolAddress((void**)&v,   g_v);
    cudaGetSymbolAddress((void**)&att, g_att);
    cudaGetSymbolAddress((void**)&x2,  g_x2);
    cudaGetSymbolAddress((void**)&y,   g_y);
    cudaGetSymbolAddress((void**)&hbuf,g_h);
    cudaGetSymbolAddress((void**)&wq,  g_wq);
    cudaGetSymbolAddress((void**)&wk,  g_wk);
    cudaGetSymbolAddress((void**)&wv,  g_wv);

    // 1. repack QKV weights [H,C,D] -> [C,H*D]
    repack3_kernel<<<(HEADS * CDIM * HD + 255) / 256, 256>>>(Wq, Wk, Wv, wq, wk, wv);

    // 2. LN1
    ln_kernel<<<NTOK, 256>>>(x, ln1_g, ln1_b, xn);

    // 3. Q/K/V projections
    {
        dim3 grid(CDIM / 128, NTOK / 128);
        sgemm_kernel<0,0,0><<<grid, 256>>>(xn, wq, nullptr, nullptr, q, NTOK, CDIM, CDIM);
        sgemm_kernel<0,0,0><<<grid, 256>>>(xn, wk, nullptr, nullptr, k, NTOK, CDIM, CDIM);
        sgemm_kernel<0,0,0><<<grid, 256>>>(xn, wv, nullptr, nullptr, v, NTOK, CDIM, CDIM);
    }

    // 4. attention
    {
        dim3 grid(TSEQ / 64, BB * HEADS);
        flash_kernel<<<grid, 256>>>(q, k, v, att);
    }

    // 5. output projection + bias + residual(x) -> x2
    {
        dim3 grid(CDIM / 128, NTOK / 128);
        sgemm_kernel<0,1,1><<<grid, 256>>>(att, Wo, bo, x, x2, NTOK, CDIM, CDIM);
    }

    // 6. LN2
    ln_kernel<<<NTOK, 256>>>(x2, ln2_g, ln2_b, y);

    // 7. FC1 + bias + GELU
    {
        dim3 grid(MLPD / 128, NTOK / 128);
        sgemm_kernel<1,1,0><<<grid, 256>>>(y, W1, b1, nullptr, hbuf, NTOK, MLPD, CDIM);
    }

    // 8. FC2 + bias + residual(x2) -> out
    {
        dim3 grid(CDIM / 128, NTOK / 128);
        sgemm_kernel<0,1,1><<<grid, 256>>>(hbuf, W2, b2, x2, out, NTOK, CDIM, MLPD);
    }
}

// round 3
// speedup vs baseline: 1.3750x; 1.3750x over previous
#include <cuda_runtime.h>
#include <math.h>
#include <stdint.h>

// Problem constants
#define BB    4
#define TSEQ  2048
#define CDIM  768
#define HEADS 12
#define HD    64
#define MLPD  3072
#define NTOK  (BB*TSEQ)          // 8192
#define QKVN  (3*CDIM)           // 2304

// ---------------------------------------------------------------------------
// Scratch (device globals; no allocation allowed)
// ---------------------------------------------------------------------------
__device__ float g_xn  [NTOK*CDIM];
__device__ float g_qkv [NTOK*QKVN];
__device__ float g_att [NTOK*CDIM];
__device__ float g_x2  [NTOK*CDIM];
__device__ float g_y   [NTOK*CDIM];
__device__ float g_h   [NTOK*MLPD];
__device__ float g_wqkv[CDIM*QKVN];

// ---------------------------------------------------------------------------
// Repack [H,C,D] x3 -> fused [C, 3*H*D]
// ---------------------------------------------------------------------------
__global__ void repackqkv_kernel(const float* __restrict__ wq,
                                 const float* __restrict__ wk,
                                 const float* __restrict__ wv,
                                 float* __restrict__ o) {
    int i = blockIdx.x * 256 + threadIdx.x;
    if (i >= HEADS * CDIM * HD) return;
    int h = i / (CDIM * HD);
    int r = i % (CDIM * HD);
    int c = r / HD;
    int d = r % HD;
    size_t base = (size_t)c * QKVN + h * HD + d;
    o[base]            = wq[i];
    o[base + CDIM]     = wk[i];
    o[base + 2*CDIM]   = wv[i];
}

// ---------------------------------------------------------------------------
// LayerNorm: one block per token row, 256 threads, C=768 -> 3 elems/thread
// ---------------------------------------------------------------------------
__global__ void ln_kernel(const float* __restrict__ x,
                          const float* __restrict__ g,
                          const float* __restrict__ b,
                          float* __restrict__ out) {
    int row = blockIdx.x;
    int tid = threadIdx.x;
    const float* xr = x + (size_t)row * CDIM;

    float v0 = xr[tid];
    float v1 = xr[tid + 256];
    float v2 = xr[tid + 512];
    float s  = v0 + v1 + v2;
    float s2 = v0*v0 + v1*v1 + v2*v2;

    #pragma unroll
    for (int o = 16; o > 0; o >>= 1) {
        s  += __shfl_xor_sync(0xffffffffu, s,  o);
        s2 += __shfl_xor_sync(0xffffffffu, s2, o);
    }
    __shared__ float rs[8], rs2[8];
    int w = tid >> 5, l = tid & 31;
    if (l == 0) { rs[w] = s; rs2[w] = s2; }
    __syncthreads();
    if (tid < 32) {
        float a  = (l < 8) ? rs[l]  : 0.f;
        float a2 = (l < 8) ? rs2[l] : 0.f;
        #pragma unroll
        for (int o = 4; o > 0; o >>= 1) {
            a  += __shfl_xor_sync(0xffffffffu, a,  o);
            a2 += __shfl_xor_sync(0xffffffffu, a2, o);
        }
        if (l == 0) { rs[0] = a; rs2[0] = a2; }
    }
    __syncthreads();
    float mu  = rs[0] * (1.f / CDIM);
    float var = rs2[0] * (1.f / CDIM) - mu * mu;
    float inv = rsqrtf(var + 1e-6f);

    float* orow = out + (size_t)row * CDIM;
    orow[tid]       = (v0 - mu) * inv * g[tid]       + b[tid];
    orow[tid + 256] = (v1 - mu) * inv * g[tid + 256] + b[tid + 256];
    orow[tid + 512] = (v2 - mu) * inv * g[tid + 512] + b[tid + 512];
}

// ---------------------------------------------------------------------------
// TF32 tensor-core GEMM: C = act(A[M,K] @ B[K,N] + bias) + res
// 128x128 tile, BK=32, 256 threads (8 warps 2x4), mma.m16n8k8.tf32
// ---------------------------------------------------------------------------
__device__ __forceinline__ float gelu_exact(float v) {
    return 0.5f * v * (1.0f + erff(v * 0.70710678118654752f));
}

__device__ __forceinline__ uint32_t f2tf32(float f) {
    uint32_t u;
    asm("cvt.rna.tf32.f32 %0, %1;" : "=r"(u) : "f"(f));
    return u;
}

#define SMS 136   // smem row stride (floats); 136 % 32 == 8 -> conflict-free frag loads

template<int ACT, int HASBIAS, int HASRES>
__global__ void __launch_bounds__(256, 1)
tgemm_kernel(const float* __restrict__ A, const float* __restrict__ B,
             const float* __restrict__ bias, const float* __restrict__ res,
             float* __restrict__ C, int M, int N, int K) {
    __shared__ uint32_t sA[32 * SMS];   // [k][m], k 0..31, m 0..127
    __shared__ uint32_t sB[32 * SMS];   // [k][n]

    int tid  = threadIdx.x;
    int lane = tid & 31;
    int warp = tid >> 5;
    int wm = warp >> 2;            // 0..1 -> 64 rows each
    int wn = warp & 3;             // 0..3 -> 32 cols each
    int m0 = blockIdx.y * 128, n0 = blockIdx.x * 128;

    // A staging: thread handles (row = tid>>1, k half = (tid&1)*16)
    int arow = tid >> 1;
    int akb  = (tid & 1) * 16;
    const float* Ap = A + (size_t)(m0 + arow) * K + akb;
    // B staging: thread handles (k row = tid&31, n chunk = (tid>>5)*16)
    int brow = tid & 31;
    int bnb  = (tid >> 5) * 16;
    const float* Bp = B + (size_t)brow * N + n0 + bnb;

    float4 as[4], bs[4];
    #pragma unroll
    for (int i = 0; i < 4; i++) {
        as[i] = *(const float4*)(Ap + i * 4);
        bs[i] = *(const float4*)(Bp + i * 4);
    }

    float acc[4][4][4];            // [mt][nt][creg]
    #pragma unroll
    for (int a = 0; a < 4; a++)
        #pragma unroll
        for (int b = 0; b < 4; b++)
            #pragma unroll
            for (int c = 0; c < 4; c++) acc[a][b][c] = 0.f;

    for (int k0 = 0; k0 < K; k0 += 32) {
        __syncthreads();
        // scatter-store staged A (transpose to [k][m]) with tf32 conversion
        #pragma unroll
        for (int i = 0; i < 4; i++) {
            const float* f = (const float*)&as[i];
            #pragma unroll
            for (int j = 0; j < 4; j++) {
                int k = akb + i * 4 + j;
                sA[k * SMS + arow] = f2tf32(f[j]);
            }
        }
        // store staged B ([k][n]) with tf32 conversion
        #pragma unroll
        for (int i = 0; i < 4; i++) {
            const float* f = (const float*)&bs[i];
            #pragma unroll
            for (int j = 0; j < 4; j++) {
                int n = bnb + i * 4 + j;
                sB[brow * SMS + n] = f2tf32(f[j]);
            }
        }
        __syncthreads();

        // prefetch next K-slab into registers (latency hidden by compute)
        if (k0 + 32 < K) {
            #pragma unroll
            for (int i = 0; i < 4; i++) {
                as[i] = *(const float4*)(Ap + (k0 + 32) + i * 4);
                bs[i] = *(const float4*)(Bp + (size_t)(k0 + 32) * N + i * 4);
            }
        }

        #pragma unroll
        for (int ks = 0; ks < 4; ks++) {
            int kb = ks * 8 + (lane & 3);
            uint32_t bf[4][2];
            #pragma unroll
            for (int nt = 0; nt < 4; nt++) {
                int gn = wn * 32 + nt * 8 + (lane >> 2);
                bf[nt][0] = sB[kb * SMS + gn];
                bf[nt][1] = sB[(kb + 4) * SMS + gn];
            }
            uint32_t af[4][4];
            #pragma unroll
            for (int mt = 0; mt < 4; mt++) {
                int gm = wm * 64 + mt * 16 + (lane >> 2);
                af[mt][0] = sA[kb * SMS + gm];
                af[mt][1] = sA[kb * SMS + gm + 8];
                af[mt][2] = sA[(kb + 4) * SMS + gm];
                af[mt][3] = sA[(kb + 4) * SMS + gm + 8];
            }
            #pragma unroll
            for (int mt = 0; mt < 4; mt++)
                #pragma unroll
                for (int nt = 0; nt < 4; nt++) {
                    float* d = acc[mt][nt];
                    asm volatile(
                        "mma.sync.aligned.m16n8k8.row.col.f32.tf32.tf32.f32 "
                        "{%0,%1,%2,%3}, {%4,%5,%6,%7}, {%8,%9}, {%0,%1,%2,%3};"
                        : "+f"(d[0]), "+f"(d[1]), "+f"(d[2]), "+f"(d[3])
                        : "r"(af[mt][0]), "r"(af[mt][1]), "r"(af[mt][2]), "r"(af[mt][3]),
                          "r"(bf[nt][0]), "r"(bf[nt][1]));
                }
        }
    }

    // Epilogue: c0,c1 at (r, gc..gc+1); c2,c3 at (r+8, gc..gc+1)
    #pragma unroll
    for (int mt = 0; mt < 4; mt++) {
        int gr = m0 + wm * 64 + mt * 16 + (lane >> 2);
        #pragma unroll
        for (int nt = 0; nt < 4; nt++) {
            int gc = n0 + wn * 32 + nt * 8 + (lane & 3) * 2;
            float2 v0, v1;
            v0.x = acc[mt][nt][0]; v0.y = acc[mt][nt][1];
            v1.x = acc[mt][nt][2]; v1.y = acc[mt][nt][3];
            if (HASBIAS) {
                float2 bb = *(const float2*)&bias[gc];
                v0.x += bb.x; v0.y += bb.y;
                v1.x += bb.x; v1.y += bb.y;
            }
            if (ACT == 1) {
                v0.x = gelu_exact(v0.x); v0.y = gelu_exact(v0.y);
                v1.x = gelu_exact(v1.x); v1.y = gelu_exact(v1.y);
            }
            if (HASRES) {
                float2 r0 = *(const float2*)&res[(size_t)gr * N + gc];
                float2 r1 = *(const float2*)&res[(size_t)(gr + 8) * N + gc];
                v0.x += r0.x; v0.y += r0.y;
                v1.x += r1.x; v1.y += r1.y;
            }
            *(float2*)&C[(size_t)gr * N + gc]       = v0;
            *(float2*)&C[(size_t)(gr + 8) * N + gc] = v1;
        }
    }
}

// ---------------------------------------------------------------------------
// Flash attention (no mask): per (b,h), BR=64 query rows/block, BC=32 kv tile.
// Q/K/V live in fused qkv buffer with row stride QKVN; O has stride CDIM.
// ---------------------------------------------------------------------------
__global__ void __launch_bounds__(256, 4)
flash_kernel(const float* __restrict__ Q, const float* __restrict__ K,
             const float* __restrict__ V, float* __restrict__ O) {
    __shared__ float sq [64 * 64];   // q tile  [r][d], stride 64
    __shared__ float skp[32 * 68];   // k tile  [s][d] stride 68 ; later p [r][j] stride 32
    __shared__ float sv [32 * 68];   // v tile  [s][d], stride 68

    int tid = threadIdx.x;
    int tx = tid & 15, ty = tid >> 4;
    int bh = blockIdx.y;
    int b = bh / HEADS, h = bh % HEADS;
    int t0 = blockIdx.x * 64;
    size_t base  = (size_t)b * TSEQ * QKVN + (size_t)h * HD;
    size_t obase = (size_t)b * TSEQ * CDIM + (size_t)h * HD;

    // load q tile (64 x 64)
    #pragma unroll
    for (int it = 0; it < 4; it++) {
        int vi = tid + 256 * it;
        int r = vi >> 4;
        int cq = (vi & 15) * 4;
        *(float4*)&sq[r * 64 + cq] =
            *(const float4*)&Q[base + (size_t)(t0 + r) * QKVN + cq];
    }

    float acc[4][4];
    float rm[4], rl[4];
    #pragma unroll
    for (int r = 0; r < 4; r++) {
        rm[r] = -1e30f; rl[r] = 0.f;
        #pragma unroll
        for (int c = 0; c < 4; c++) acc[r][c] = 0.f;
    }
    const float scale = 0.03608439182435161f;   // 768^-0.5

    for (int kt = 0; kt < TSEQ / 32; kt++) {
        int s0 = kt * 32;
        __syncthreads();   // prior-iteration p/v reads done
        #pragma unroll
        for (int it = 0; it < 2; it++) {
            int vi = tid + 256 * it;
            int r = vi >> 4;
            int cq = (vi & 15) * 4;
            size_t goff = base + (size_t)(s0 + r) * QKVN + cq;
            *(float4*)&skp[r * 68 + cq] = *(const float4*)&K[goff];
            *(float4*)&sv [r * 68 + cq] = *(const float4*)&V[goff];
        }
        __syncthreads();

        // S = Q K^T : thread covers rows 4*ty..+3, cols 2*tx..+1
        float sacc[4][2];
        #pragma unroll
        for (int r = 0; r < 4; r++) { sacc[r][0] = 0.f; sacc[r][1] = 0.f; }
        #pragma unroll
        for (int d = 0; d < 64; d += 4) {
            float4 qa[4], kb[2];
            #pragma unroll
            for (int r = 0; r < 4; r++) qa[r] = *(float4*)&sq[(ty * 4 + r) * 64 + d];
            #pragma unroll
            for (int c = 0; c < 2; c++) kb[c] = *(float4*)&skp[(tx * 2 + c) * 68 + d];
            #pragma unroll
            for (int r = 0; r < 4; r++) {
                #pragma unroll
                for (int c = 0; c < 2; c++) {
                    sacc[r][c] += qa[r].x * kb[c].x + qa[r].y * kb[c].y
                                + qa[r].z * kb[c].z + qa[r].w * kb[c].w;
                }
            }
        }

        // online softmax stats (per row; reduce over 16 tx lanes = half-warp)
        float p[4][2];
        #pragma unroll
        for (int r = 0; r < 4; r++) {
            float srow0 = sacc[r][0] * scale;
            float srow1 = sacc[r][1] * scale;
            float mx = fmaxf(srow0, srow1);
            #pragma unroll
            for (int o = 8; o > 0; o >>= 1)
                mx = fmaxf(mx, __shfl_xor_sync(0xffffffffu, mx, o));
            float mnew = fmaxf(rm[r], mx);
            float alpha = __expf(rm[r] - mnew);
            p[r][0] = __expf(srow0 - mnew);
            p[r][1] = __expf(srow1 - mnew);
            float sm = p[r][0] + p[r][1];
            #pragma unroll
            for (int o = 8; o > 0; o >>= 1)
                sm += __shfl_xor_sync(0xffffffffu, sm, o);
            rl[r] = rl[r] * alpha + sm;
            rm[r] = mnew;
            #pragma unroll
            for (int c = 0; c < 4; c++) acc[r][c] *= alpha;
        }

        __syncthreads();   // all K reads done; safe to overwrite skp with P
        #pragma unroll
        for (int r = 0; r < 4; r++) {
            skp[(ty * 4 + r) * 32 + tx * 2 + 0] = p[r][0];
            skp[(ty * 4 + r) * 32 + tx * 2 + 1] = p[r][1];
        }
        __syncthreads();

        // O += P V : thread covers rows 4*ty..+3, d cols 4*tx..+3
        #pragma unroll
        for (int j = 0; j < 32; j += 4) {
            float4 pr[4];
            float vvf[4][4];
            #pragma unroll
            for (int r = 0; r < 4; r++)
                pr[r] = *(float4*)&skp[(ty * 4 + r) * 32 + j];
            #pragma unroll
            for (int jj = 0; jj < 4; jj++) {
                float4 t = *(float4*)&sv[(j + jj) * 68 + tx * 4];
                vvf[jj][0] = t.x; vvf[jj][1] = t.y; vvf[jj][2] = t.z; vvf[jj][3] = t.w;
            }
            #pragma unroll
            for (int r = 0; r < 4; r++) {
                #pragma unroll
                for (int c = 0; c < 4; c++) {
                    acc[r][c] += pr[r].x * vvf[0][c] + pr[r].y * vvf[1][c]
                               + pr[r].z * vvf[2][c] + pr[r].w * vvf[3][c];
                }
            }
        }
    }

    // epilogue: O = acc / l
    #pragma unroll
    for (int r = 0; r < 4; r++) {
        float inv = 1.f / rl[r];
        int row = t0 + ty * 4 + r;
        float4 o4;
        o4.x = acc[r][0] * inv;
        o4.y = acc[r][1] * inv;
        o4.z = acc[r][2] * inv;
        o4.w = acc[r][3] * inv;
        *(float4*)&O[obase + (size_t)row * CDIM + tx * 4] = o4;
    }
}

// ---------------------------------------------------------------------------
// Launch
// ---------------------------------------------------------------------------
extern "C" void kernel_launch(void* const* d_in, const int* in_sizes, int n_in,
                              void* d_out, int out_size) {
    const float* x     = (const float*)d_in[0];
    const float* Wq    = (const float*)d_in[1];
    const float* Wk    = (const float*)d_in[2];
    const float* Wv    = (const float*)d_in[3];
    const float* Wo    = (const float*)d_in[4];
    const float* bo    = (const float*)d_in[5];
    const float* ln1_g = (const float*)d_in[6];
    const float* ln1_b = (const float*)d_in[7];
    const float* ln2_g = (const float*)d_in[8];
    const float* ln2_b = (const float*)d_in[9];
    const float* W1    = (const float*)d_in[10];
    const float* b1    = (const float*)d_in[11];
    const float* W2    = (const float*)d_in[12];
    const float* b2    = (const float*)d_in[13];
    float* out = (float*)d_out;

    float *xn, *qkv, *att, *x2, *y, *hbuf, *wqkv;
    cudaGetSymbolAddress((void**)&xn,   g_xn);
    cudaGetSymbolAddress((void**)&qkv,  g_qkv);
    cudaGetSymbolAddress((void**)&att,  g_att);
    cudaGetSymbolAddress((void**)&x2,   g_x2);
    cudaGetSymbolAddress((void**)&y,    g_y);
    cudaGetSymbolAddress((void**)&hbuf, g_h);
    cudaGetSymbolAddress((void**)&wqkv, g_wqkv);

    // 1. repack QKV weights into fused [C, 3*H*D]
    repackqkv_kernel<<<(HEADS * CDIM * HD + 255) / 256, 256>>>(Wq, Wk, Wv, wqkv);

    // 2. LN1
    ln_kernel<<<NTOK, 256>>>(x, ln1_g, ln1_b, xn);

    // 3. fused QKV projection: [8192,768] x [768,2304]
    {
        dim3 grid(QKVN / 128, NTOK / 128);
        tgemm_kernel<0,0,0><<<grid, 256>>>(xn, wqkv, nullptr, nullptr, qkv,
                                           NTOK, QKVN, CDIM);
    }

    // 4. attention (Q/K/V strided views into qkv)
    {
        dim3 grid(TSEQ / 64, BB * HEADS);
        flash_kernel<<<grid, 256>>>(qkv, qkv + CDIM, qkv + 2 * CDIM, att);
    }

    // 5. output projection + bias + residual(x) -> x2
    {
        dim3 grid(CDIM / 128, NTOK / 128);
        tgemm_kernel<0,1,1><<<grid, 256>>>(att, Wo, bo, x, x2, NTOK, CDIM, CDIM);
    }

    // 6. LN2
    ln_kernel<<<NTOK, 256>>>(x2, ln2_g, ln2_b, y);

    // 7. FC1 + bias + GELU
    {
        dim3 grid(MLPD / 128, NTOK / 128);
        tgemm_kernel<1,1,0><<<grid, 256>>>(y, W1, b1, nullptr, hbuf,
                                           NTOK, MLPD, CDIM);
    }

    // 8. FC2 + bias + residual(x2) -> out
    {
        dim3 grid(CDIM / 128, NTOK / 128);
        tgemm_kernel<0,1,1><<<grid, 256>>>(hbuf, W2, b2, x2, out,
                                           NTOK, CDIM, MLPD);
    }
}

// round 5
// speedup vs baseline: 1.9622x; 1.4270x over previous
#include <cuda_runtime.h>
#include <math.h>
#include <stdint.h>

// Problem constants
#define BB    4
#define TSEQ  2048
#define CDIM  768
#define HEADS 12
#define HD    64
#define MLPD  3072
#define NTOK  (BB*TSEQ)          // 8192
#define QKVN  (3*CDIM)           // 2304

// ---------------------------------------------------------------------------
// Scratch (device globals; no allocation allowed)
// ---------------------------------------------------------------------------
__device__ float g_xn  [NTOK*CDIM];
__device__ float g_qkv [NTOK*QKVN];
__device__ float g_att [NTOK*CDIM];
__device__ float g_x2  [NTOK*CDIM];
__device__ float g_y   [NTOK*CDIM];
__device__ float g_h   [NTOK*MLPD];
__device__ float g_wqkv[CDIM*QKVN];

// ---------------------------------------------------------------------------
// Repack [H,C,D] x3 -> fused [C, 3*H*D]
// ---------------------------------------------------------------------------
__global__ void repackqkv_kernel(const float* __restrict__ wq,
                                 const float* __restrict__ wk,
                                 const float* __restrict__ wv,
                                 float* __restrict__ o) {
    int i = blockIdx.x * 256 + threadIdx.x;
    if (i >= HEADS * CDIM * HD) return;
    int h = i / (CDIM * HD);
    int r = i % (CDIM * HD);
    int c = r / HD;
    int d = r % HD;
    size_t base = (size_t)c * QKVN + h * HD + d;
    o[base]            = wq[i];
    o[base + CDIM]     = wk[i];
    o[base + 2*CDIM]   = wv[i];
}

// ---------------------------------------------------------------------------
// LayerNorm: one block per token row, 256 threads, C=768 -> 3 elems/thread
// ---------------------------------------------------------------------------
__global__ void ln_kernel(const float* __restrict__ x,
                          const float* __restrict__ g,
                          const float* __restrict__ b,
                          float* __restrict__ out) {
    int row = blockIdx.x;
    int tid = threadIdx.x;
    const float* xr = x + (size_t)row * CDIM;

    float v0 = xr[tid];
    float v1 = xr[tid + 256];
    float v2 = xr[tid + 512];
    float s  = v0 + v1 + v2;
    float s2 = v0*v0 + v1*v1 + v2*v2;

    #pragma unroll
    for (int o = 16; o > 0; o >>= 1) {
        s  += __shfl_xor_sync(0xffffffffu, s,  o);
        s2 += __shfl_xor_sync(0xffffffffu, s2, o);
    }
    __shared__ float rs[8], rs2[8];
    int w = tid >> 5, l = tid & 31;
    if (l == 0) { rs[w] = s; rs2[w] = s2; }
    __syncthreads();
    if (tid < 32) {
        float a  = (l < 8) ? rs[l]  : 0.f;
        float a2 = (l < 8) ? rs2[l] : 0.f;
        #pragma unroll
        for (int o = 4; o > 0; o >>= 1) {
            a  += __shfl_xor_sync(0xffffffffu, a,  o);
            a2 += __shfl_xor_sync(0xffffffffu, a2, o);
        }
        if (l == 0) { rs[0] = a; rs2[0] = a2; }
    }
    __syncthreads();
    float mu  = rs[0] * (1.f / CDIM);
    float var = rs2[0] * (1.f / CDIM) - mu * mu;
    float inv = rsqrtf(var + 1e-6f);

    float* orow = out + (size_t)row * CDIM;
    orow[tid]       = (v0 - mu) * inv * g[tid]       + b[tid];
    orow[tid + 256] = (v1 - mu) * inv * g[tid + 256] + b[tid + 256];
    orow[tid + 512] = (v2 - mu) * inv * g[tid + 512] + b[tid + 512];
}

// ---------------------------------------------------------------------------
// Common helpers
// ---------------------------------------------------------------------------
__device__ __forceinline__ float gelu_exact(float v) {
    return 0.5f * v * (1.0f + erff(v * 0.70710678118654752f));
}

__device__ __forceinline__ uint32_t f2tf32(float f) {
    uint32_t u;
    asm("cvt.rna.tf32.f32 %0, %1;" : "=r"(u) : "f"(f));
    return u;
}

#define MMA_TF32(d, a0,a1,a2,a3, b0,b1)                                      \
    asm volatile(                                                            \
        "mma.sync.aligned.m16n8k8.row.col.f32.tf32.tf32.f32 "                \
        "{%0,%1,%2,%3}, {%4,%5,%6,%7}, {%8,%9}, {%0,%1,%2,%3};"              \
        : "+f"(d[0]), "+f"(d[1]), "+f"(d[2]), "+f"(d[3])                     \
        : "r"(a0), "r"(a1), "r"(a2), "r"(a3), "r"(b0), "r"(b1))

// ---------------------------------------------------------------------------
// TF32 tensor-core GEMM: C = act(A[M,K] @ B[K,N] + bias) + res
// 128x128 tile, BK=32, 256 threads (8 warps 2x4), mma.m16n8k8.tf32
// ---------------------------------------------------------------------------
#define SMS 136   // smem row stride (floats); 136 % 32 == 8 -> conflict-free frag loads

template<int ACT, int HASBIAS, int HASRES>
__global__ void __launch_bounds__(256, 1)
tgemm_kernel(const float* __restrict__ A, const float* __restrict__ B,
             const float* __restrict__ bias, const float* __restrict__ res,
             float* __restrict__ C, int M, int N, int K) {
    __shared__ uint32_t sA[32 * SMS];   // [k][m], k 0..31, m 0..127
    __shared__ uint32_t sB[32 * SMS];   // [k][n]

    int tid  = threadIdx.x;
    int lane = tid & 31;
    int warp = tid >> 5;
    int wm = warp >> 2;            // 0..1 -> 64 rows each
    int wn = warp & 3;             // 0..3 -> 32 cols each
    int m0 = blockIdx.y * 128, n0 = blockIdx.x * 128;

    int arow = tid >> 1;
    int akb  = (tid & 1) * 16;
    const float* Ap = A + (size_t)(m0 + arow) * K + akb;
    int brow = tid & 31;
    int bnb  = (tid >> 5) * 16;
    const float* Bp = B + (size_t)brow * N + n0 + bnb;

    float4 as[4], bs[4];
    #pragma unroll
    for (int i = 0; i < 4; i++) {
        as[i] = *(const float4*)(Ap + i * 4);
        bs[i] = *(const float4*)(Bp + i * 4);
    }

    float acc[4][4][4];
    #pragma unroll
    for (int a = 0; a < 4; a++)
        #pragma unroll
        for (int b = 0; b < 4; b++)
            #pragma unroll
            for (int c = 0; c < 4; c++) acc[a][b][c] = 0.f;

    for (int k0 = 0; k0 < K; k0 += 32) {
        __syncthreads();
        #pragma unroll
        for (int i = 0; i < 4; i++) {
            const float* f = (const float*)&as[i];
            #pragma unroll
            for (int j = 0; j < 4; j++) {
                int k = akb + i * 4 + j;
                sA[k * SMS + arow] = f2tf32(f[j]);
            }
        }
        #pragma unroll
        for (int i = 0; i < 4; i++) {
            const float* f = (const float*)&bs[i];
            #pragma unroll
            for (int j = 0; j < 4; j++) {
                int n = bnb + i * 4 + j;
                sB[brow * SMS + n] = f2tf32(f[j]);
            }
        }
        __syncthreads();

        if (k0 + 32 < K) {
            #pragma unroll
            for (int i = 0; i < 4; i++) {
                as[i] = *(const float4*)(Ap + (k0 + 32) + i * 4);
                bs[i] = *(const float4*)(Bp + (size_t)(k0 + 32) * N + i * 4);
            }
        }

        #pragma unroll
        for (int ks = 0; ks < 4; ks++) {
            int kb = ks * 8 + (lane & 3);
            uint32_t bf[4][2];
            #pragma unroll
            for (int nt = 0; nt < 4; nt++) {
                int gn = wn * 32 + nt * 8 + (lane >> 2);
                bf[nt][0] = sB[kb * SMS + gn];
                bf[nt][1] = sB[(kb + 4) * SMS + gn];
            }
            uint32_t af[4][4];
            #pragma unroll
            for (int mt = 0; mt < 4; mt++) {
                int gm = wm * 64 + mt * 16 + (lane >> 2);
                af[mt][0] = sA[kb * SMS + gm];
                af[mt][1] = sA[kb * SMS + gm + 8];
                af[mt][2] = sA[(kb + 4) * SMS + gm];
                af[mt][3] = sA[(kb + 4) * SMS + gm + 8];
            }
            #pragma unroll
            for (int mt = 0; mt < 4; mt++)
                #pragma unroll
                for (int nt = 0; nt < 4; nt++) {
                    float* d = acc[mt][nt];
                    MMA_TF32(d, af[mt][0], af[mt][1], af[mt][2], af[mt][3],
                             bf[nt][0], bf[nt][1]);
                }
        }
    }

    #pragma unroll
    for (int mt = 0; mt < 4; mt++) {
        int gr = m0 + wm * 64 + mt * 16 + (lane >> 2);
        #pragma unroll
        for (int nt = 0; nt < 4; nt++) {
            int gc = n0 + wn * 32 + nt * 8 + (lane & 3) * 2;
            float2 v0, v1;
            v0.x = acc[mt][nt][0]; v0.y = acc[mt][nt][1];
            v1.x = acc[mt][nt][2]; v1.y = acc[mt][nt][3];
            if (HASBIAS) {
                float2 bb = *(const float2*)&bias[gc];
                v0.x += bb.x; v0.y += bb.y;
                v1.x += bb.x; v1.y += bb.y;
            }
            if (ACT == 1) {
                v0.x = gelu_exact(v0.x); v0.y = gelu_exact(v0.y);
                v1.x = gelu_exact(v1.x); v1.y = gelu_exact(v1.y);
            }
            if (HASRES) {
                float2 r0 = *(const float2*)&res[(size_t)gr * N + gc];
                float2 r1 = *(const float2*)&res[(size_t)(gr + 8) * N + gc];
                v0.x += r0.x; v0.y += r0.y;
                v1.x += r1.x; v1.y += r1.y;
            }
            *(float2*)&C[(size_t)gr * N + gc]       = v0;
            *(float2*)&C[(size_t)(gr + 8) * N + gc] = v1;
        }
    }
}

// ---------------------------------------------------------------------------
// Tensor-core flash attention (no mask), TF32 mma.m16n8k8.
// Per (b,h): BR=64 query rows / block, BC=64 kv tile, 4 warps (16 rows each).
// Q/K/V strided views into fused qkv buffer (row stride QKVN); O stride CDIM.
// smem: buf0 = K^T [d][s]  (later overwritten by P [s][m]) ; buf1 = V [s][d].
// Q is pre-scaled, staged once via buf0, then kept in registers as A-frags.
// ---------------------------------------------------------------------------
#define FSTR 72   // 72 % 32 == 8 -> conflict-free fragment accesses

__global__ void __launch_bounds__(128, 1)
flash_tc_kernel(const float* __restrict__ Q, const float* __restrict__ K,
                const float* __restrict__ V, float* __restrict__ O) {
    __shared__ uint32_t buf0[64 * FSTR];   // K^T [d][s] / P [s][m] / Q^T staging
    __shared__ uint32_t buf1[64 * FSTR];   // V [s][d]

    int tid  = threadIdx.x;
    int lane = tid & 31;
    int w    = tid >> 5;               // warp 0..3 -> q rows 16w..16w+15
    int g    = lane >> 2;              // row-in-group 0..7
    int t4   = lane & 3;               // k/col group 0..3

    int bh = blockIdx.y;
    int b = bh / HEADS, h = bh % HEADS;
    int t0 = blockIdx.x * 64;
    size_t base  = (size_t)b * TSEQ * QKVN + (size_t)h * HD;
    size_t obase = (size_t)b * TSEQ * CDIM + (size_t)h * HD;

    const float scale = 0.03608439182435161f;   // 768^-0.5

    // ---- stage Q (pre-scaled) transposed into buf0, extract A-fragments ----
    #pragma unroll
    for (int it = 0; it < 8; it++) {
        int idx = tid + 128 * it;          // 0..1023
        int r  = idx >> 4;                 // 0..63
        int dq = (idx & 15) * 4;
        float4 qv = *(const float4*)&Q[base + (size_t)(t0 + r) * QKVN + dq];
        buf0[(dq + 0) * FSTR + r] = f2tf32(qv.x * scale);
        buf0[(dq + 1) * FSTR + r] = f2tf32(qv.y * scale);
        buf0[(dq + 2) * FSTR + r] = f2tf32(qv.z * scale);
        buf0[(dq + 3) * FSTR + r] = f2tf32(qv.w * scale);
    }
    __syncthreads();

    uint32_t qf[8][4];
    #pragma unroll
    for (int ks = 0; ks < 8; ks++) {
        int kb = ks * 8 + t4;
        int gm = 16 * w + g;
        qf[ks][0] = buf0[kb * FSTR + gm];
        qf[ks][1] = buf0[kb * FSTR + gm + 8];
        qf[ks][2] = buf0[(kb + 4) * FSTR + gm];
        qf[ks][3] = buf0[(kb + 4) * FSTR + gm + 8];
    }

    // online-softmax state (two row-halves per thread: rows g and g+8 of warp tile)
    float o_acc[8][4];
    #pragma unroll
    for (int nt = 0; nt < 8; nt++)
        #pragma unroll
        for (int c = 0; c < 4; c++) o_acc[nt][c] = 0.f;
    float rm0 = -1e30f, rm1 = -1e30f, rl0 = 0.f, rl1 = 0.f;

    for (int kt = 0; kt < TSEQ / 64; kt++) {
        int s0 = kt * 64;
        __syncthreads();   // buf0(P) reads + buf1(V) reads of prev iter done

        // load K -> buf0 transposed [d][s]; V -> buf1 direct [s][d]
        #pragma unroll
        for (int it = 0; it < 8; it++) {
            int idx = tid + 128 * it;
            int r  = idx >> 4;             // kv row 0..63
            int dq = (idx & 15) * 4;
            size_t goff = base + (size_t)(s0 + r) * QKVN + dq;
            float4 kv4 = *(const float4*)&K[goff];
            float4 vv4 = *(const float4*)&V[goff];
            buf0[(dq + 0) * FSTR + r] = f2tf32(kv4.x);
            buf0[(dq + 1) * FSTR + r] = f2tf32(kv4.y);
            buf0[(dq + 2) * FSTR + r] = f2tf32(kv4.z);
            buf0[(dq + 3) * FSTR + r] = f2tf32(kv4.w);
            buf1[r * FSTR + dq + 0] = f2tf32(vv4.x);
            buf1[r * FSTR + dq + 1] = f2tf32(vv4.y);
            buf1[r * FSTR + dq + 2] = f2tf32(vv4.z);
            buf1[r * FSTR + dq + 3] = f2tf32(vv4.w);
        }
        __syncthreads();

        // ---- S = Q K^T  (16 x 64 per warp) ----
        float sacc[8][4];
        #pragma unroll
        for (int nt = 0; nt < 8; nt++)
            #pragma unroll
            for (int c = 0; c < 4; c++) sacc[nt][c] = 0.f;

        #pragma unroll
        for (int ks = 0; ks < 8; ks++) {
            int kb = ks * 8 + t4;
            uint32_t bf[8][2];
            #pragma unroll
            for (int nt = 0; nt < 8; nt++) {
                int gn = nt * 8 + g;
                bf[nt][0] = buf0[kb * FSTR + gn];
                bf[nt][1] = buf0[(kb + 4) * FSTR + gn];
            }
            #pragma unroll
            for (int nt = 0; nt < 8; nt++) {
                float* d = sacc[nt];
                MMA_TF32(d, qf[ks][0], qf[ks][1], qf[ks][2], qf[ks][3],
                         bf[nt][0], bf[nt][1]);
            }
        }
        __syncthreads();   // all warps done reading K; buf0 free for P

        // ---- online softmax on fragments ----
        float mx0 = -1e30f, mx1 = -1e30f;
        #pragma unroll
        for (int nt = 0; nt < 8; nt++) {
            mx0 = fmaxf(mx0, fmaxf(sacc[nt][0], sacc[nt][1]));
            mx1 = fmaxf(mx1, fmaxf(sacc[nt][2], sacc[nt][3]));
        }
        mx0 = fmaxf(mx0, __shfl_xor_sync(0xffffffffu, mx0, 1));
        mx0 = fmaxf(mx0, __shfl_xor_sync(0xffffffffu, mx0, 2));
        mx1 = fmaxf(mx1, __shfl_xor_sync(0xffffffffu, mx1, 1));
        mx1 = fmaxf(mx1, __shfl_xor_sync(0xffffffffu, mx1, 2));

        float mn0 = fmaxf(rm0, mx0);
        float mn1 = fmaxf(rm1, mx1);
        float al0 = __expf(rm0 - mn0);
        float al1 = __expf(rm1 - mn1);
        rm0 = mn0; rm1 = mn1;

        int row0 = 16 * w + g;
        int row1 = row0 + 8;
        float sum0 = 0.f, sum1 = 0.f;
        #pragma unroll
        for (int nt = 0; nt < 8; nt++) {
            int col = nt * 8 + 2 * t4;
            float p0 = __expf(sacc[nt][0] - mn0);
            float p1 = __expf(sacc[nt][1] - mn0);
            float p2 = __expf(sacc[nt][2] - mn1);
            float p3 = __expf(sacc[nt][3] - mn1);
            sum0 += p0 + p1;
            sum1 += p2 + p3;
            buf0[(col + 0) * FSTR + row0] = f2tf32(p0);
            buf0[(col + 1) * FSTR + row0] = f2tf32(p1);
            buf0[(col + 0) * FSTR + row1] = f2tf32(p2);
            buf0[(col + 1) * FSTR + row1] = f2tf32(p3);
        }
        sum0 += __shfl_xor_sync(0xffffffffu, sum0, 1);
        sum0 += __shfl_xor_sync(0xffffffffu, sum0, 2);
        sum1 += __shfl_xor_sync(0xffffffffu, sum1, 1);
        sum1 += __shfl_xor_sync(0xffffffffu, sum1, 2);
        rl0 = rl0 * al0 + sum0;
        rl1 = rl1 * al1 + sum1;

        #pragma unroll
        for (int nt = 0; nt < 8; nt++) {
            o_acc[nt][0] *= al0; o_acc[nt][1] *= al0;
            o_acc[nt][2] *= al1; o_acc[nt][3] *= al1;
        }
        __syncwarp();   // P stores visible within warp

        // ---- O += P V  (A = P from buf0, B = V from buf1) ----
        #pragma unroll
        for (int ks = 0; ks < 8; ks++) {
            int kb = ks * 8 + t4;
            int gm = 16 * w + g;
            uint32_t af0 = buf0[kb * FSTR + gm];
            uint32_t af1 = buf0[kb * FSTR + gm + 8];
            uint32_t af2 = buf0[(kb + 4) * FSTR + gm];
            uint32_t af3 = buf0[(kb + 4) * FSTR + gm + 8];
            uint32_t bf[8][2];
            #pragma unroll
            for (int nt = 0; nt < 8; nt++) {
                int gn = nt * 8 + g;
                bf[nt][0] = buf1[kb * FSTR + gn];
                bf[nt][1] = buf1[(kb + 4) * FSTR + gn];
            }
            #pragma unroll
            for (int nt = 0; nt < 8; nt++) {
                float* d = o_acc[nt];
                MMA_TF32(d, af0, af1, af2, af3, bf[nt][0], bf[nt][1]);
            }
        }
    }

    // ---- epilogue: O = acc / l ----
    float inv0 = 1.f / rl0;
    float inv1 = 1.f / rl1;
    int row0 = t0 + 16 * w + g;
    int row1 = row0 + 8;
    #pragma unroll
    for (int nt = 0; nt < 8; nt++) {
        int dcol = nt * 8 + 2 * t4;
        float2 v0, v1;
        v0.x = o_acc[nt][0] * inv0; v0.y = o_acc[nt][1] * inv0;
        v1.x = o_acc[nt][2] * inv1; v1.y = o_acc[nt][3] * inv1;
        *(float2*)&O[obase + (size_t)row0 * CDIM + dcol] = v0;
        *(float2*)&O[obase + (size_t)row1 * CDIM + dcol] = v1;
    }
}

// ---------------------------------------------------------------------------
// Launch
// ---------------------------------------------------------------------------
extern "C" void kernel_launch(void* const* d_in, const int* in_sizes, int n_in,
                              void* d_out, int out_size) {
    const float* x     = (const float*)d_in[0];
    const float* Wq    = (const float*)d_in[1];
    const float* Wk    = (const float*)d_in[2];
    const float* Wv    = (const float*)d_in[3];
    const float* Wo    = (const float*)d_in[4];
    const float* bo    = (const float*)d_in[5];
    const float* ln1_g = (const float*)d_in[6];
    const float* ln1_b = (const float*)d_in[7];
    const float* ln2_g = (const float*)d_in[8];
    const float* ln2_b = (const float*)d_in[9];
    const float* W1    = (const float*)d_in[10];
    const float* b1    = (const float*)d_in[11];
    const float* W2    = (const float*)d_in[12];
    const float* b2    = (const float*)d_in[13];
    float* out = (float*)d_out;

    float *xn, *qkv, *att, *x2, *y, *hbuf, *wqkv;
    cudaGetSymbolAddress((void**)&xn,   g_xn);
    cudaGetSymbolAddress((void**)&qkv,  g_qkv);
    cudaGetSymbolAddress((void**)&att,  g_att);
    cudaGetSymbolAddress((void**)&x2,   g_x2);
    cudaGetSymbolAddress((void**)&y,    g_y);
    cudaGetSymbolAddress((void**)&hbuf, g_h);
    cudaGetSymbolAddress((void**)&wqkv, g_wqkv);

    // 1. repack QKV weights into fused [C, 3*H*D]
    repackqkv_kernel<<<(HEADS * CDIM * HD + 255) / 256, 256>>>(Wq, Wk, Wv, wqkv);

    // 2. LN1
    ln_kernel<<<NTOK, 256>>>(x, ln1_g, ln1_b, xn);

    // 3. fused QKV projection: [8192,768] x [768,2304]
    {
        dim3 grid(QKVN / 128, NTOK / 128);
        tgemm_kernel<0,0,0><<<grid, 256>>>(xn, wqkv, nullptr, nullptr, qkv,
                                           NTOK, QKVN, CDIM);
    }

    // 4. tensor-core flash attention (Q/K/V strided views into qkv)
    {
        dim3 grid(TSEQ / 64, BB * HEADS);
        flash_tc_kernel<<<grid, 128>>>(qkv, qkv + CDIM, qkv + 2 * CDIM, att);
    }

    // 5. output projection + bias + residual(x) -> x2
    {
        dim3 grid(CDIM / 128, NTOK / 128);
        tgemm_kernel<0,1,1><<<grid, 256>>>(att, Wo, bo, x, x2, NTOK, CDIM, CDIM);
    }

    // 6. LN2
    ln_kernel<<<NTOK, 256>>>(x2, ln2_g, ln2_b, y);

    // 7. FC1 + bias + GELU
    {
        dim3 grid(MLPD / 128, NTOK / 128);
        tgemm_kernel<1,1,0><<<grid, 256>>>(y, W1, b1, nullptr, hbuf,
                                           NTOK, MLPD, CDIM);
    }

    // 8. FC2 + bias + residual(x2) -> out
    {
        dim3 grid(CDIM / 128, NTOK / 128);
        tgemm_kernel<0,1,1><<<grid, 256>>>(hbuf, W2, b2, x2, out,
                                           NTOK, CDIM, MLPD);
    }
}

// round 6
// speedup vs baseline: 2.1113x; 1.0760x over previous
#include <cuda_runtime.h>
#include <math.h>
#include <stdint.h>

// Problem constants
#define BB    4
#define TSEQ  2048
#define CDIM  768
#define HEADS 12
#define HD    64
#define MLPD  3072
#define NTOK  (BB*TSEQ)          // 8192
#define QKVN  (3*CDIM)           // 2304

// ---------------------------------------------------------------------------
// Scratch (device globals; no allocation allowed)
// ---------------------------------------------------------------------------
__device__ float g_xn  [NTOK*CDIM];
__device__ float g_qkv [NTOK*QKVN];
__device__ float g_att [NTOK*CDIM];
__device__ float g_x2  [NTOK*CDIM];
__device__ float g_y   [NTOK*CDIM];
__device__ float g_h   [NTOK*MLPD];
__device__ float g_wqkv[CDIM*QKVN];

// ---------------------------------------------------------------------------
// Repack [H,C,D] x3 -> fused [C, 3*H*D]
// ---------------------------------------------------------------------------
__global__ void repackqkv_kernel(const float* __restrict__ wq,
                                 const float* __restrict__ wk,
                                 const float* __restrict__ wv,
                                 float* __restrict__ o) {
    int i = blockIdx.x * 256 + threadIdx.x;
    if (i >= HEADS * CDIM * HD) return;
    int h = i / (CDIM * HD);
    int r = i % (CDIM * HD);
    int c = r / HD;
    int d = r % HD;
    size_t base = (size_t)c * QKVN + h * HD + d;
    o[base]            = wq[i];
    o[base + CDIM]     = wk[i];
    o[base + 2*CDIM]   = wv[i];
}

// ---------------------------------------------------------------------------
// LayerNorm: one block per token row, 256 threads, C=768 -> 3 elems/thread
// ---------------------------------------------------------------------------
__global__ void ln_kernel(const float* __restrict__ x,
                          const float* __restrict__ g,
                          const float* __restrict__ b,
                          float* __restrict__ out) {
    int row = blockIdx.x;
    int tid = threadIdx.x;
    const float* xr = x + (size_t)row * CDIM;

    float v0 = xr[tid];
    float v1 = xr[tid + 256];
    float v2 = xr[tid + 512];
    float s  = v0 + v1 + v2;
    float s2 = v0*v0 + v1*v1 + v2*v2;

    #pragma unroll
    for (int o = 16; o > 0; o >>= 1) {
        s  += __shfl_xor_sync(0xffffffffu, s,  o);
        s2 += __shfl_xor_sync(0xffffffffu, s2, o);
    }
    __shared__ float rs[8], rs2[8];
    int w = tid >> 5, l = tid & 31;
    if (l == 0) { rs[w] = s; rs2[w] = s2; }
    __syncthreads();
    if (tid < 32) {
        float a  = (l < 8) ? rs[l]  : 0.f;
        float a2 = (l < 8) ? rs2[l] : 0.f;
        #pragma unroll
        for (int o = 4; o > 0; o >>= 1) {
            a  += __shfl_xor_sync(0xffffffffu, a,  o);
            a2 += __shfl_xor_sync(0xffffffffu, a2, o);
        }
        if (l == 0) { rs[0] = a; rs2[0] = a2; }
    }
    __syncthreads();
    float mu  = rs[0] * (1.f / CDIM);
    float var = rs2[0] * (1.f / CDIM) - mu * mu;
    float inv = rsqrtf(var + 1e-6f);

    float* orow = out + (size_t)row * CDIM;
    orow[tid]       = (v0 - mu) * inv * g[tid]       + b[tid];
    orow[tid + 256] = (v1 - mu) * inv * g[tid + 256] + b[tid + 256];
    orow[tid + 512] = (v2 - mu) * inv * g[tid + 512] + b[tid + 512];
}

// ---------------------------------------------------------------------------
// Common helpers
// ---------------------------------------------------------------------------
__device__ __forceinline__ float gelu_exact(float v) {
    return 0.5f * v * (1.0f + erff(v * 0.70710678118654752f));
}

__device__ __forceinline__ uint32_t f2tf32(float f) {
    uint32_t u;
    asm("cvt.rna.tf32.f32 %0, %1;" : "=r"(u) : "f"(f));
    return u;
}

#define MMA_TF32(d, a0,a1,a2,a3, b0,b1)                                      \
    asm volatile(                                                            \
        "mma.sync.aligned.m16n8k8.row.col.f32.tf32.tf32.f32 "                \
        "{%0,%1,%2,%3}, {%4,%5,%6,%7}, {%8,%9}, {%0,%1,%2,%3};"              \
        : "+f"(d[0]), "+f"(d[1]), "+f"(d[2]), "+f"(d[3])                     \
        : "r"(a0), "r"(a1), "r"(a2), "r"(a3), "r"(b0), "r"(b1))

// ---------------------------------------------------------------------------
// TF32 tensor-core GEMM: C = act(A[M,K] @ B[K,N] + bias) + res
// 128x128 tile, BK=32, 256 threads (8 warps 2x4), mma.m16n8k8.tf32
// ---------------------------------------------------------------------------
#define SMS 136   // smem row stride (floats); 136 % 32 == 8 -> conflict-free frag loads

template<int ACT, int HASBIAS, int HASRES>
__global__ void __launch_bounds__(256, 1)
tgemm_kernel(const float* __restrict__ A, const float* __restrict__ B,
             const float* __restrict__ bias, const float* __restrict__ res,
             float* __restrict__ C, int M, int N, int K) {
    __shared__ uint32_t sA[32 * SMS];   // [k][m], k 0..31, m 0..127
    __shared__ uint32_t sB[32 * SMS];   // [k][n]

    int tid  = threadIdx.x;
    int lane = tid & 31;
    int warp = tid >> 5;
    int wm = warp >> 2;            // 0..1 -> 64 rows each
    int wn = warp & 3;             // 0..3 -> 32 cols each
    int m0 = blockIdx.y * 128, n0 = blockIdx.x * 128;

    int arow = tid >> 1;
    int akb  = (tid & 1) * 16;
    const float* Ap = A + (size_t)(m0 + arow) * K + akb;
    int brow = tid & 31;
    int bnb  = (tid >> 5) * 16;
    const float* Bp = B + (size_t)brow * N + n0 + bnb;

    float4 as[4], bs[4];
    #pragma unroll
    for (int i = 0; i < 4; i++) {
        as[i] = *(const float4*)(Ap + i * 4);
        bs[i] = *(const float4*)(Bp + i * 4);
    }

    float acc[4][4][4];
    #pragma unroll
    for (int a = 0; a < 4; a++)
        #pragma unroll
        for (int b = 0; b < 4; b++)
            #pragma unroll
            for (int c = 0; c < 4; c++) acc[a][b][c] = 0.f;

    for (int k0 = 0; k0 < K; k0 += 32) {
        __syncthreads();
        #pragma unroll
        for (int i = 0; i < 4; i++) {
            const float* f = (const float*)&as[i];
            #pragma unroll
            for (int j = 0; j < 4; j++) {
                int k = akb + i * 4 + j;
                sA[k * SMS + arow] = f2tf32(f[j]);
            }
        }
        #pragma unroll
        for (int i = 0; i < 4; i++) {
            const float* f = (const float*)&bs[i];
            #pragma unroll
            for (int j = 0; j < 4; j++) {
                int n = bnb + i * 4 + j;
                sB[brow * SMS + n] = f2tf32(f[j]);
            }
        }
        __syncthreads();

        if (k0 + 32 < K) {
            #pragma unroll
            for (int i = 0; i < 4; i++) {
                as[i] = *(const float4*)(Ap + (k0 + 32) + i * 4);
                bs[i] = *(const float4*)(Bp + (size_t)(k0 + 32) * N + i * 4);
            }
        }

        #pragma unroll
        for (int ks = 0; ks < 4; ks++) {
            int kb = ks * 8 + (lane & 3);
            uint32_t bf[4][2];
            #pragma unroll
            for (int nt = 0; nt < 4; nt++) {
                int gn = wn * 32 + nt * 8 + (lane >> 2);
                bf[nt][0] = sB[kb * SMS + gn];
                bf[nt][1] = sB[(kb + 4) * SMS + gn];
            }
            uint32_t af[4][4];
            #pragma unroll
            for (int mt = 0; mt < 4; mt++) {
                int gm = wm * 64 + mt * 16 + (lane >> 2);
                af[mt][0] = sA[kb * SMS + gm];
                af[mt][1] = sA[kb * SMS + gm + 8];
                af[mt][2] = sA[(kb + 4) * SMS + gm];
                af[mt][3] = sA[(kb + 4) * SMS + gm + 8];
            }
            #pragma unroll
            for (int mt = 0; mt < 4; mt++)
                #pragma unroll
                for (int nt = 0; nt < 4; nt++) {
                    float* d = acc[mt][nt];
                    MMA_TF32(d, af[mt][0], af[mt][1], af[mt][2], af[mt][3],
                             bf[nt][0], bf[nt][1]);
                }
        }
    }

    #pragma unroll
    for (int mt = 0; mt < 4; mt++) {
        int gr = m0 + wm * 64 + mt * 16 + (lane >> 2);
        #pragma unroll
        for (int nt = 0; nt < 4; nt++) {
            int gc = n0 + wn * 32 + nt * 8 + (lane & 3) * 2;
            float2 v0, v1;
            v0.x = acc[mt][nt][0]; v0.y = acc[mt][nt][1];
            v1.x = acc[mt][nt][2]; v1.y = acc[mt][nt][3];
            if (HASBIAS) {
                float2 bb = *(const float2*)&bias[gc];
                v0.x += bb.x; v0.y += bb.y;
                v1.x += bb.x; v1.y += bb.y;
            }
            if (ACT == 1) {
                v0.x = gelu_exact(v0.x); v0.y = gelu_exact(v0.y);
                v1.x = gelu_exact(v1.x); v1.y = gelu_exact(v1.y);
            }
            if (HASRES) {
                float2 r0 = *(const float2*)&res[(size_t)gr * N + gc];
                float2 r1 = *(const float2*)&res[(size_t)(gr + 8) * N + gc];
                v0.x += r0.x; v0.y += r0.y;
                v1.x += r1.x; v1.y += r1.y;
            }
            *(float2*)&C[(size_t)gr * N + gc]       = v0;
            *(float2*)&C[(size_t)(gr + 8) * N + gc] = v1;
        }
    }
}

// ---------------------------------------------------------------------------
// Tensor-core flash attention v2 (no mask), TF32 mma.m16n8k8.
// Per (b,h): BR=128 query rows / block (8 warps x 16 rows), BC=64 kv tile.
// Dynamic smem (53.2KB):
//   pk [64][136] : Q^T staging -> per-iter K^T [d][s] -> P [s][m 0..127]
//   sv [64][72]  : V [s][d]
// K^T/Q^T staging uses r-major lane mapping -> conflict-free stores
// (bank = 8j + r, r distinct per lane). V uses coalesced mapping (~2-way).
// ---------------------------------------------------------------------------
#define PKS 136   // 136 % 32 == 8 -> conflict-free fragment reads
#define SVS 72    //  72 % 32 == 8 -> conflict-free fragment reads
#define FLASH_SMEM ((64*PKS + 64*SVS) * 4)

__global__ void __launch_bounds__(256, 1)
flash_tc_kernel(const float* __restrict__ Q, const float* __restrict__ K,
                const float* __restrict__ V, float* __restrict__ O) {
    extern __shared__ uint32_t smf[];
    uint32_t* pk = smf;              // 64 * PKS
    uint32_t* sv = smf + 64 * PKS;   // 64 * SVS

    int tid  = threadIdx.x;
    int lane = tid & 31;
    int w    = tid >> 5;               // warp 0..7 -> q rows 16w..16w+15
    int g    = lane >> 2;              // 0..7
    int t4   = lane & 3;               // 0..3

    int bh = blockIdx.y;
    int b = bh / HEADS, h = bh % HEADS;
    int t0 = blockIdx.x * 128;
    size_t base  = (size_t)b * TSEQ * QKVN + (size_t)h * HD;
    size_t obase = (size_t)b * TSEQ * CDIM + (size_t)h * HD;

    const float scale = 0.03608439182435161f;   // 768^-0.5

    // ---- stage Q^T (pre-scaled) into pk: r-major mapping, conflict-free ----
    #pragma unroll
    for (int it = 0; it < 8; it++) {
        int idx = tid + 256 * it;          // 0..2047 over 128 rows x 16 dq
        int r  = idx & 127;                // q row 0..127
        int dq = (idx >> 7) * 4;           // 0..60
        float4 qv = *(const float4*)&Q[base + (size_t)(t0 + r) * QKVN + dq];
        pk[(dq + 0) * PKS + r] = f2tf32(qv.x * scale);
        pk[(dq + 1) * PKS + r] = f2tf32(qv.y * scale);
        pk[(dq + 2) * PKS + r] = f2tf32(qv.z * scale);
        pk[(dq + 3) * PKS + r] = f2tf32(qv.w * scale);
    }
    __syncthreads();

    uint32_t qf[8][4];
    #pragma unroll
    for (int ks = 0; ks < 8; ks++) {
        int kb = ks * 8 + t4;
        int gm = 16 * w + g;
        qf[ks][0] = pk[kb * PKS + gm];
        qf[ks][1] = pk[kb * PKS + gm + 8];
        qf[ks][2] = pk[(kb + 4) * PKS + gm];
        qf[ks][3] = pk[(kb + 4) * PKS + gm + 8];
    }

    float o_acc[8][4];
    #pragma unroll
    for (int nt = 0; nt < 8; nt++)
        #pragma unroll
        for (int c = 0; c < 4; c++) o_acc[nt][c] = 0.f;
    float rm0 = -1e30f, rm1 = -1e30f, rl0 = 0.f, rl1 = 0.f;

    for (int kt = 0; kt < TSEQ / 64; kt++) {
        int s0 = kt * 64;
        __syncthreads();   // prev-iter P/V reads (and initial qf extraction) done

        // K -> pk transposed [d][s] (r-major lanes: conflict-free stores)
        #pragma unroll
        for (int it = 0; it < 4; it++) {
            int idx = tid + 256 * it;      // 0..1023 over 64 rows x 16 dq
            int r  = idx & 63;
            int dq = (idx >> 6) * 4;
            float4 kv4 = *(const float4*)&K[base + (size_t)(s0 + r) * QKVN + dq];
            pk[(dq + 0) * PKS + r] = f2tf32(kv4.x);
            pk[(dq + 1) * PKS + r] = f2tf32(kv4.y);
            pk[(dq + 2) * PKS + r] = f2tf32(kv4.z);
            pk[(dq + 3) * PKS + r] = f2tf32(kv4.w);
        }
        // V -> sv direct [s][d] (coalesced reads)
        #pragma unroll
        for (int it = 0; it < 4; it++) {
            int idx = tid + 256 * it;
            int r  = idx >> 4;             // 0..63
            int dv = (idx & 15) * 4;
            float4 vv4 = *(const float4*)&V[base + (size_t)(s0 + r) * QKVN + dv];
            sv[r * SVS + dv + 0] = f2tf32(vv4.x);
            sv[r * SVS + dv + 1] = f2tf32(vv4.y);
            sv[r * SVS + dv + 2] = f2tf32(vv4.z);
            sv[r * SVS + dv + 3] = f2tf32(vv4.w);
        }
        __syncthreads();

        // ---- S = Q K^T  (16 x 64 per warp) ----
        float sacc[8][4];
        #pragma unroll
        for (int nt = 0; nt < 8; nt++)
            #pragma unroll
            for (int c = 0; c < 4; c++) sacc[nt][c] = 0.f;

        #pragma unroll
        for (int ks = 0; ks < 8; ks++) {
            int kb = ks * 8 + t4;
            uint32_t bf[8][2];
            #pragma unroll
            for (int nt = 0; nt < 8; nt++) {
                int gn = nt * 8 + g;
                bf[nt][0] = pk[kb * PKS + gn];
                bf[nt][1] = pk[(kb + 4) * PKS + gn];
            }
            #pragma unroll
            for (int nt = 0; nt < 8; nt++) {
                float* d = sacc[nt];
                MMA_TF32(d, qf[ks][0], qf[ks][1], qf[ks][2], qf[ks][3],
                         bf[nt][0], bf[nt][1]);
            }
        }
        __syncthreads();   // all warps done reading K^T; pk free for P

        // ---- online softmax on fragments ----
        float mx0 = -1e30f, mx1 = -1e30f;
        #pragma unroll
        for (int nt = 0; nt < 8; nt++) {
            mx0 = fmaxf(mx0, fmaxf(sacc[nt][0], sacc[nt][1]));
            mx1 = fmaxf(mx1, fmaxf(sacc[nt][2], sacc[nt][3]));
        }
        mx0 = fmaxf(mx0, __shfl_xor_sync(0xffffffffu, mx0, 1));
        mx0 = fmaxf(mx0, __shfl_xor_sync(0xffffffffu, mx0, 2));
        mx1 = fmaxf(mx1, __shfl_xor_sync(0xffffffffu, mx1, 1));
        mx1 = fmaxf(mx1, __shfl_xor_sync(0xffffffffu, mx1, 2));

        float mn0 = fmaxf(rm0, mx0);
        float mn1 = fmaxf(rm1, mx1);
        float al0 = __expf(rm0 - mn0);
        float al1 = __expf(rm1 - mn1);
        rm0 = mn0; rm1 = mn1;

        int row0 = 16 * w + g;
        int row1 = row0 + 8;
        float sum0 = 0.f, sum1 = 0.f;
        #pragma unroll
        for (int nt = 0; nt < 8; nt++) {
            int col = nt * 8 + 2 * t4;
            float p0 = __expf(sacc[nt][0] - mn0);
            float p1 = __expf(sacc[nt][1] - mn0);
            float p2 = __expf(sacc[nt][2] - mn1);
            float p3 = __expf(sacc[nt][3] - mn1);
            sum0 += p0 + p1;
            sum1 += p2 + p3;
            pk[(col + 0) * PKS + row0] = f2tf32(p0);
            pk[(col + 1) * PKS + row0] = f2tf32(p1);
            pk[(col + 0) * PKS + row1] = f2tf32(p2);
            pk[(col + 1) * PKS + row1] = f2tf32(p3);
        }
        sum0 += __shfl_xor_sync(0xffffffffu, sum0, 1);
        sum0 += __shfl_xor_sync(0xffffffffu, sum0, 2);
        sum1 += __shfl_xor_sync(0xffffffffu, sum1, 1);
        sum1 += __shfl_xor_sync(0xffffffffu, sum1, 2);
        rl0 = rl0 * al0 + sum0;
        rl1 = rl1 * al1 + sum1;

        #pragma unroll
        for (int nt = 0; nt < 8; nt++) {
            o_acc[nt][0] *= al0; o_acc[nt][1] *= al0;
            o_acc[nt][2] *= al1; o_acc[nt][3] *= al1;
        }
        __syncwarp();   // P stores visible within warp (each warp reads own rows)

        // ---- O += P V  (A = P from pk, B = V from sv) ----
        #pragma unroll
        for (int ks = 0; ks < 8; ks++) {
            int kb = ks * 8 + t4;
            int gm = 16 * w + g;
            uint32_t af0 = pk[kb * PKS + gm];
            uint32_t af1 = pk[kb * PKS + gm + 8];
            uint32_t af2 = pk[(kb + 4) * PKS + gm];
            uint32_t af3 = pk[(kb + 4) * PKS + gm + 8];
            uint32_t bf[8][2];
            #pragma unroll
            for (int nt = 0; nt < 8; nt++) {
                int gn = nt * 8 + g;
                bf[nt][0] = sv[kb * SVS + gn];
                bf[nt][1] = sv[(kb + 4) * SVS + gn];
            }
            #pragma unroll
            for (int nt = 0; nt < 8; nt++) {
                float* d = o_acc[nt];
                MMA_TF32(d, af0, af1, af2, af3, bf[nt][0], bf[nt][1]);
            }
        }
    }

    // ---- epilogue: O = acc / l ----
    float inv0 = 1.f / rl0;
    float inv1 = 1.f / rl1;
    int row0 = t0 + 16 * w + g;
    int row1 = row0 + 8;
    #pragma unroll
    for (int nt = 0; nt < 8; nt++) {
        int dcol = nt * 8 + 2 * t4;
        float2 v0, v1;
        v0.x = o_acc[nt][0] * inv0; v0.y = o_acc[nt][1] * inv0;
        v1.x = o_acc[nt][2] * inv1; v1.y = o_acc[nt][3] * inv1;
        *(float2*)&O[obase + (size_t)row0 * CDIM + dcol] = v0;
        *(float2*)&O[obase + (size_t)row1 * CDIM + dcol] = v1;
    }
}

// ---------------------------------------------------------------------------
// Launch
// ---------------------------------------------------------------------------
extern "C" void kernel_launch(void* const* d_in, const int* in_sizes, int n_in,
                              void* d_out, int out_size) {
    const float* x     = (const float*)d_in[0];
    const float* Wq    = (const float*)d_in[1];
    const float* Wk    = (const float*)d_in[2];
    const float* Wv    = (const float*)d_in[3];
    const float* Wo    = (const float*)d_in[4];
    const float* bo    = (const float*)d_in[5];
    const float* ln1_g = (const float*)d_in[6];
    const float* ln1_b = (const float*)d_in[7];
    const float* ln2_g = (const float*)d_in[8];
    const float* ln2_b = (const float*)d_in[9];
    const float* W1    = (const float*)d_in[10];
    const float* b1    = (const float*)d_in[11];
    const float* W2    = (const float*)d_in[12];
    const float* b2    = (const float*)d_in[13];
    float* out = (float*)d_out;

    float *xn, *qkv, *att, *x2, *y, *hbuf, *wqkv;
    cudaGetSymbolAddress((void**)&xn,   g_xn);
    cudaGetSymbolAddress((void**)&qkv,  g_qkv);
    cudaGetSymbolAddress((void**)&att,  g_att);
    cudaGetSymbolAddress((void**)&x2,   g_x2);
    cudaGetSymbolAddress((void**)&y,    g_y);
    cudaGetSymbolAddress((void**)&hbuf, g_h);
    cudaGetSymbolAddress((void**)&wqkv, g_wqkv);

    static bool attr_done = false;
    if (!attr_done) {
        cudaFuncSetAttribute(flash_tc_kernel,
                             cudaFuncAttributeMaxDynamicSharedMemorySize,
                             FLASH_SMEM);
        attr_done = true;
    }

    // 1. repack QKV weights into fused [C, 3*H*D]
    repackqkv_kernel<<<(HEADS * CDIM * HD + 255) / 256, 256>>>(Wq, Wk, Wv, wqkv);

    // 2. LN1
    ln_kernel<<<NTOK, 256>>>(x, ln1_g, ln1_b, xn);

    // 3. fused QKV projection: [8192,768] x [768,2304]
    {
        dim3 grid(QKVN / 128, NTOK / 128);
        tgemm_kernel<0,0,0><<<grid, 256>>>(xn, wqkv, nullptr, nullptr, qkv,
                                           NTOK, QKVN, CDIM);
    }

    // 4. tensor-core flash attention (Q/K/V strided views into qkv)
    {
        dim3 grid(TSEQ / 128, BB * HEADS);
        flash_tc_kernel<<<grid, 256, FLASH_SMEM>>>(qkv, qkv + CDIM,
                                                   qkv + 2 * CDIM, att);
    }

    // 5. output projection + bias + residual(x) -> x2
    {
        dim3 grid(CDIM / 128, NTOK / 128);
        tgemm_kernel<0,1,1><<<grid, 256>>>(att, Wo, bo, x, x2, NTOK, CDIM, CDIM);
    }

    // 6. LN2
    ln_kernel<<<NTOK, 256>>>(x2, ln2_g, ln2_b, y);

    // 7. FC1 + bias + GELU
    {
        dim3 grid(MLPD / 128, NTOK / 128);
        tgemm_kernel<1,1,0><<<grid, 256>>>(y, W1, b1, nullptr, hbuf,
                                           NTOK, MLPD, CDIM);
    }

    // 8. FC2 + bias + residual(x2) -> out
    {
        dim3 grid(CDIM / 128, NTOK / 128);
        tgemm_kernel<0,1,1><<<grid, 256>>>(hbuf, W2, b2, x2, out,
                                           NTOK, CDIM, MLPD);
    }
}

// round 7
// speedup vs baseline: 2.1776x; 1.0314x over previous
#include <cuda_runtime.h>
#include <math.h>
#include <stdint.h>

// Problem constants
#define BB    4
#define TSEQ  2048
#define CDIM  768
#define HEADS 12
#define HD    64
#define MLPD  3072
#define NTOK  (BB*TSEQ)          // 8192
#define QKVN  (3*CDIM)           // 2304

// ---------------------------------------------------------------------------
// Scratch (device globals; no allocation allowed)
// ---------------------------------------------------------------------------
__device__ float g_xn  [NTOK*CDIM];
__device__ float g_qkv [NTOK*QKVN];
__device__ float g_att [NTOK*CDIM];
__device__ float g_x2  [NTOK*CDIM];
__device__ float g_y   [NTOK*CDIM];
__device__ float g_h   [NTOK*MLPD];
__device__ float g_wqkv[CDIM*QKVN];

// ---------------------------------------------------------------------------
// Repack [H,C,D] x3 -> fused [C, 3*H*D]
// ---------------------------------------------------------------------------
__global__ void repackqkv_kernel(const float* __restrict__ wq,
                                 const float* __restrict__ wk,
                                 const float* __restrict__ wv,
                                 float* __restrict__ o) {
    int i = blockIdx.x * 256 + threadIdx.x;
    if (i >= HEADS * CDIM * HD) return;
    int h = i / (CDIM * HD);
    int r = i % (CDIM * HD);
    int c = r / HD;
    int d = r % HD;
    size_t base = (size_t)c * QKVN + h * HD + d;
    o[base]            = wq[i];
    o[base + CDIM]     = wk[i];
    o[base + 2*CDIM]   = wv[i];
}

// ---------------------------------------------------------------------------
// LayerNorm: one block per token row, 256 threads, C=768 -> 3 elems/thread
// ---------------------------------------------------------------------------
__global__ void ln_kernel(const float* __restrict__ x,
                          const float* __restrict__ g,
                          const float* __restrict__ b,
                          float* __restrict__ out) {
    int row = blockIdx.x;
    int tid = threadIdx.x;
    const float* xr = x + (size_t)row * CDIM;

    float v0 = xr[tid];
    float v1 = xr[tid + 256];
    float v2 = xr[tid + 512];
    float s  = v0 + v1 + v2;
    float s2 = v0*v0 + v1*v1 + v2*v2;

    #pragma unroll
    for (int o = 16; o > 0; o >>= 1) {
        s  += __shfl_xor_sync(0xffffffffu, s,  o);
        s2 += __shfl_xor_sync(0xffffffffu, s2, o);
    }
    __shared__ float rs[8], rs2[8];
    int w = tid >> 5, l = tid & 31;
    if (l == 0) { rs[w] = s; rs2[w] = s2; }
    __syncthreads();
    if (tid < 32) {
        float a  = (l < 8) ? rs[l]  : 0.f;
        float a2 = (l < 8) ? rs2[l] : 0.f;
        #pragma unroll
        for (int o = 4; o > 0; o >>= 1) {
            a  += __shfl_xor_sync(0xffffffffu, a,  o);
            a2 += __shfl_xor_sync(0xffffffffu, a2, o);
        }
        if (l == 0) { rs[0] = a; rs2[0] = a2; }
    }
    __syncthreads();
    float mu  = rs[0] * (1.f / CDIM);
    float var = rs2[0] * (1.f / CDIM) - mu * mu;
    float inv = rsqrtf(var + 1e-6f);

    float* orow = out + (size_t)row * CDIM;
    orow[tid]       = (v0 - mu) * inv * g[tid]       + b[tid];
    orow[tid + 256] = (v1 - mu) * inv * g[tid + 256] + b[tid + 256];
    orow[tid + 512] = (v2 - mu) * inv * g[tid + 512] + b[tid + 512];
}

// ---------------------------------------------------------------------------
// Common helpers
// ---------------------------------------------------------------------------
__device__ __forceinline__ float gelu_exact(float v) {
    return 0.5f * v * (1.0f + erff(v * 0.70710678118654752f));
}

__device__ __forceinline__ uint32_t f2tf32(float f) {
    uint32_t u;
    asm("cvt.rna.tf32.f32 %0, %1;" : "=r"(u) : "f"(f));
    return u;
}

#define MMA_TF32(d, a0,a1,a2,a3, b0,b1)                                      \
    asm volatile(                                                            \
        "mma.sync.aligned.m16n8k8.row.col.f32.tf32.tf32.f32 "                \
        "{%0,%1,%2,%3}, {%4,%5,%6,%7}, {%8,%9}, {%0,%1,%2,%3};"              \
        : "+f"(d[0]), "+f"(d[1]), "+f"(d[2]), "+f"(d[3])                     \
        : "r"(a0), "r"(a1), "r"(a2), "r"(a3), "r"(b0), "r"(b1))

// ---------------------------------------------------------------------------
// TF32 tensor-core GEMM: C = act(A[M,K] @ B[K,N] + bias) + res
// 128x128 tile, BK=32, 256 threads (8 warps 2x4), mma.m16n8k8.tf32
// Conflict-free smem staging via XOR swizzles:
//   A [k][m]: element logical-k stored at k ^ (2*((k>>4)&1))
//   B [k][n]: element col e (0..15 within thread's 16-col span) stored at
//             (e&8) | ((e&7) ^ mq), mq = ((q&3)<<1)|(q>>2), q = k>>2
// ---------------------------------------------------------------------------
#define SMS 136   // smem row stride (floats); 136 % 32 == 8

__device__ __forceinline__ int mq_of(int q) {   // 3-bit bijection of q=0..7
    return ((q & 3) << 1) | (q >> 2);
}

template<int ACT, int HASBIAS, int HASRES>
__global__ void __launch_bounds__(256, 1)
tgemm_kernel(const float* __restrict__ A, const float* __restrict__ B,
             const float* __restrict__ bias, const float* __restrict__ res,
             float* __restrict__ C, int M, int N, int K) {
    __shared__ uint32_t sA[32 * SMS];   // [k][m] (k swizzled)
    __shared__ uint32_t sB[32 * SMS];   // [k][n] (n swizzled per k-quad)

    int tid  = threadIdx.x;
    int lane = tid & 31;
    int warp = tid >> 5;
    int wm = warp >> 2;            // 0..1 -> 64 rows each
    int wn = warp & 3;             // 0..3 -> 32 cols each
    int m0 = blockIdx.y * 128, n0 = blockIdx.x * 128;

    int arow = tid >> 1;
    int akb  = (tid & 1) * 16;
    int ap2  = (tid & 1) * 2;            // A store swizzle bit
    const float* Ap = A + (size_t)(m0 + arow) * K + akb;
    int brow = tid & 31;
    int bnb  = (tid >> 5) * 16;
    int bmq  = mq_of(brow >> 2);         // B store swizzle
    const float* Bp = B + (size_t)brow * N + n0 + bnb;

    float4 as[4], bs[4];
    #pragma unroll
    for (int i = 0; i < 4; i++) {
        as[i] = *(const float4*)(Ap + i * 4);
        bs[i] = *(const float4*)(Bp + i * 4);
    }

    float acc[4][4][4];
    #pragma unroll
    for (int a = 0; a < 4; a++)
        #pragma unroll
        for (int b = 0; b < 4; b++)
            #pragma unroll
            for (int c = 0; c < 4; c++) acc[a][b][c] = 0.f;

    for (int k0 = 0; k0 < K; k0 += 32) {
        __syncthreads();
        // A: element e=i*4+j (logical k = akb+e) stored at akb + (e ^ ap2)
        #pragma unroll
        for (int i = 0; i < 4; i++) {
            const float* f = (const float*)&as[i];
            #pragma unroll
            for (int j = 0; j < 4; j++) {
                int e = i * 4 + j;
                sA[(akb + (e ^ ap2)) * SMS + arow] = f2tf32(f[j]);
            }
        }
        // B: element e (logical n = bnb+e) stored at bnb + ((e&8)|((e&7)^bmq))
        #pragma unroll
        for (int i = 0; i < 4; i++) {
            const float* f = (const float*)&bs[i];
            #pragma unroll
            for (int j = 0; j < 4; j++) {
                int e = i * 4 + j;
                int col = (e & 8) | ((e & 7) ^ bmq);
                sB[brow * SMS + bnb + col] = f2tf32(f[j]);
            }
        }
        __syncthreads();

        if (k0 + 32 < K) {
            #pragma unroll
            for (int i = 0; i < 4; i++) {
                as[i] = *(const float4*)(Ap + (k0 + 32) + i * 4);
                bs[i] = *(const float4*)(Bp + (size_t)(k0 + 32) * N + i * 4);
            }
        }

        #pragma unroll
        for (int ks = 0; ks < 4; ks++) {
            int t4 = lane & 3;
            int gq = lane >> 2;
            // A read: logical kb = ks*8 + t4, stored at kb ^ (2*((kb>>4)&1));
            // bit4(kb) = (ks>>1)&1 (compile-time)
            int asw = ((ks >> 1) & 1) * 2;
            int kbA = ks * 8 + (t4 ^ asw);
            // B read: un-swizzle column per k-quad
            int kbB  = ks * 8 + t4;
            int mqr0 = mq_of((kbB >> 2) & 7);
            int mqr1 = mq_of(((kbB + 4) >> 2) & 7);

            uint32_t bf[4][2];
            #pragma unroll
            for (int nt = 0; nt < 4; nt++) {
                int gn  = wn * 32 + nt * 8;           // gq < 8 -> (gn+gq)&7 = gq
                bf[nt][0] = sB[kbB * SMS + gn + (gq ^ mqr0)];
                bf[nt][1] = sB[(kbB + 4) * SMS + gn + (gq ^ mqr1)];
            }
            uint32_t af[4][4];
            #pragma unroll
            for (int mt = 0; mt < 4; mt++) {
                int gm = wm * 64 + mt * 16 + gq;
                af[mt][0] = sA[kbA * SMS + gm];
                af[mt][1] = sA[kbA * SMS + gm + 8];
                af[mt][2] = sA[(kbA + 4) * SMS + gm];
                af[mt][3] = sA[(kbA + 4) * SMS + gm + 8];
            }
            #pragma unroll
            for (int mt = 0; mt < 4; mt++)
                #pragma unroll
                for (int nt = 0; nt < 4; nt++) {
                    float* d = acc[mt][nt];
                    MMA_TF32(d, af[mt][0], af[mt][1], af[mt][2], af[mt][3],
                             bf[nt][0], bf[nt][1]);
                }
        }
    }

    #pragma unroll
    for (int mt = 0; mt < 4; mt++) {
        int gr = m0 + wm * 64 + mt * 16 + (lane >> 2);
        #pragma unroll
        for (int nt = 0; nt < 4; nt++) {
            int gc = n0 + wn * 32 + nt * 8 + (lane & 3) * 2;
            float2 v0, v1;
            v0.x = acc[mt][nt][0]; v0.y = acc[mt][nt][1];
            v1.x = acc[mt][nt][2]; v1.y = acc[mt][nt][3];
            if (HASBIAS) {
                float2 bb = *(const float2*)&bias[gc];
                v0.x += bb.x; v0.y += bb.y;
                v1.x += bb.x; v1.y += bb.y;
            }
            if (ACT == 1) {
                v0.x = gelu_exact(v0.x); v0.y = gelu_exact(v0.y);
                v1.x = gelu_exact(v1.x); v1.y = gelu_exact(v1.y);
            }
            if (HASRES) {
                float2 r0 = *(const float2*)&res[(size_t)gr * N + gc];
                float2 r1 = *(const float2*)&res[(size_t)(gr + 8) * N + gc];
                v0.x += r0.x; v0.y += r0.y;
                v1.x += r1.x; v1.y += r1.y;
            }
            *(float2*)&C[(size_t)gr * N + gc]       = v0;
            *(float2*)&C[(size_t)(gr + 8) * N + gc] = v1;
        }
    }
}

// ---------------------------------------------------------------------------
// Tensor-core flash attention v3: register-prefetched K/V tiles.
// Per (b,h): BR=128 query rows / block (8 warps x 16 rows), BC=64 kv tile.
// Dynamic smem (53.2KB): pk[64][136] (Q^T / K^T / P), sv[64][72] (V).
// ---------------------------------------------------------------------------
#define PKS 136
#define SVS 72
#define FLASH_SMEM ((64*PKS + 64*SVS) * 4)

__global__ void __launch_bounds__(256, 1)
flash_tc_kernel(const float* __restrict__ Q, const float* __restrict__ K,
                const float* __restrict__ V, float* __restrict__ O) {
    extern __shared__ uint32_t smf[];
    uint32_t* pk = smf;              // 64 * PKS
    uint32_t* sv = smf + 64 * PKS;   // 64 * SVS

    int tid  = threadIdx.x;
    int lane = tid & 31;
    int w    = tid >> 5;
    int g    = lane >> 2;
    int t4   = lane & 3;

    int bh = blockIdx.y;
    int b = bh / HEADS, h = bh % HEADS;
    int t0 = blockIdx.x * 128;
    size_t base  = (size_t)b * TSEQ * QKVN + (size_t)h * HD;
    size_t obase = (size_t)b * TSEQ * CDIM + (size_t)h * HD;

    const float scale = 0.03608439182435161f;   // 768^-0.5

    // K loader mapping (r-major, conflict-free stores): one row per thread
    int krow = tid & 63;
    int kdq0 = (tid >> 6) * 4;           // 0,4,8,12 ; columns kdq0 + 16*it
    // V loader mapping (coalesced): r = tid>>4 + 16*it, dv fixed
    int vdv  = (tid & 15) * 4;

    // ---- stage Q^T (pre-scaled) into pk ----
    #pragma unroll
    for (int it = 0; it < 8; it++) {
        int idx = tid + 256 * it;
        int r  = idx & 127;
        int dq = (idx >> 7) * 4;
        float4 qv = *(const float4*)&Q[base + (size_t)(t0 + r) * QKVN + dq];
        pk[(dq + 0) * PKS + r] = f2tf32(qv.x * scale);
        pk[(dq + 1) * PKS + r] = f2tf32(qv.y * scale);
        pk[(dq + 2) * PKS + r] = f2tf32(qv.z * scale);
        pk[(dq + 3) * PKS + r] = f2tf32(qv.w * scale);
    }

    // preload tile 0 of K/V into registers (overlaps Q staging latency)
    float4 kreg[4], vreg[4];
    #pragma unroll
    for (int it = 0; it < 4; it++) {
        kreg[it] = *(const float4*)&K[base + (size_t)krow * QKVN + kdq0 + 16 * it];
        vreg[it] = *(const float4*)&V[base + (size_t)(tid >> 4) * QKVN +
                                      (size_t)(16 * it) * QKVN + vdv];
    }

    __syncthreads();

    uint32_t qf[8][4];
    #pragma unroll
    for (int ks = 0; ks < 8; ks++) {
        int kb = ks * 8 + t4;
        int gm = 16 * w + g;
        qf[ks][0] = pk[kb * PKS + gm];
        qf[ks][1] = pk[kb * PKS + gm + 8];
        qf[ks][2] = pk[(kb + 4) * PKS + gm];
        qf[ks][3] = pk[(kb + 4) * PKS + gm + 8];
    }

    float o_acc[8][4];
    #pragma unroll
    for (int nt = 0; nt < 8; nt++)
        #pragma unroll
        for (int c = 0; c < 4; c++) o_acc[nt][c] = 0.f;
    float rm0 = -1e30f, rm1 = -1e30f, rl0 = 0.f, rl1 = 0.f;

    const int NKT = TSEQ / 64;
    for (int kt = 0; kt < NKT; kt++) {
        __syncthreads();   // prev-iter P/V reads (and qf extraction) done

        // store prefetched K tile -> pk transposed [d][s] (conflict-free)
        #pragma unroll
        for (int it = 0; it < 4; it++) {
            int dq = kdq0 + 16 * it;
            pk[(dq + 0) * PKS + krow] = f2tf32(kreg[it].x);
            pk[(dq + 1) * PKS + krow] = f2tf32(kreg[it].y);
            pk[(dq + 2) * PKS + krow] = f2tf32(kreg[it].z);
            pk[(dq + 3) * PKS + krow] = f2tf32(kreg[it].w);
        }
        // store prefetched V tile -> sv [s][d]
        #pragma unroll
        for (int it = 0; it < 4; it++) {
            int r = (tid >> 4) + 16 * it;
            sv[r * SVS + vdv + 0] = f2tf32(vreg[it].x);
            sv[r * SVS + vdv + 1] = f2tf32(vreg[it].y);
            sv[r * SVS + vdv + 2] = f2tf32(vreg[it].z);
            sv[r * SVS + vdv + 3] = f2tf32(vreg[it].w);
        }
        __syncthreads();

        // prefetch next tile (in flight during mma/softmax below)
        if (kt + 1 < NKT) {
            size_t snext = (size_t)(kt + 1) * 64;
            #pragma unroll
            for (int it = 0; it < 4; it++) {
                kreg[it] = *(const float4*)&K[base + (snext + krow) * QKVN +
                                              kdq0 + 16 * it];
                vreg[it] = *(const float4*)&V[base + (snext + (tid >> 4) +
                                              16 * it) * QKVN + vdv];
            }
        }

        // ---- S = Q K^T  (16 x 64 per warp) ----
        float sacc[8][4];
        #pragma unroll
        for (int nt = 0; nt < 8; nt++)
            #pragma unroll
            for (int c = 0; c < 4; c++) sacc[nt][c] = 0.f;

        #pragma unroll
        for (int ks = 0; ks < 8; ks++) {
            int kb = ks * 8 + t4;
            uint32_t bf[8][2];
            #pragma unroll
            for (int nt = 0; nt < 8; nt++) {
                int gn = nt * 8 + g;
                bf[nt][0] = pk[kb * PKS + gn];
                bf[nt][1] = pk[(kb + 4) * PKS + gn];
            }
            #pragma unroll
            for (int nt = 0; nt < 8; nt++) {
                float* d = sacc[nt];
                MMA_TF32(d, qf[ks][0], qf[ks][1], qf[ks][2], qf[ks][3],
                         bf[nt][0], bf[nt][1]);
            }
        }
        __syncthreads();   // all warps done reading K^T; pk free for P

        // ---- online softmax on fragments ----
        float mx0 = -1e30f, mx1 = -1e30f;
        #pragma unroll
        for (int nt = 0; nt < 8; nt++) {
            mx0 = fmaxf(mx0, fmaxf(sacc[nt][0], sacc[nt][1]));
            mx1 = fmaxf(mx1, fmaxf(sacc[nt][2], sacc[nt][3]));
        }
        mx0 = fmaxf(mx0, __shfl_xor_sync(0xffffffffu, mx0, 1));
        mx0 = fmaxf(mx0, __shfl_xor_sync(0xffffffffu, mx0, 2));
        mx1 = fmaxf(mx1, __shfl_xor_sync(0xffffffffu, mx1, 1));
        mx1 = fmaxf(mx1, __shfl_xor_sync(0xffffffffu, mx1, 2));

        float mn0 = fmaxf(rm0, mx0);
        float mn1 = fmaxf(rm1, mx1);
        float al0 = __expf(rm0 - mn0);
        float al1 = __expf(rm1 - mn1);
        rm0 = mn0; rm1 = mn1;

        int row0 = 16 * w + g;
        int row1 = row0 + 8;
        float sum0 = 0.f, sum1 = 0.f;
        #pragma unroll
        for (int nt = 0; nt < 8; nt++) {
            int col = nt * 8 + 2 * t4;
            float p0 = __expf(sacc[nt][0] - mn0);
            float p1 = __expf(sacc[nt][1] - mn0);
            float p2 = __expf(sacc[nt][2] - mn1);
            float p3 = __expf(sacc[nt][3] - mn1);
            sum0 += p0 + p1;
            sum1 += p2 + p3;
            pk[(col + 0) * PKS + row0] = f2tf32(p0);
            pk[(col + 1) * PKS + row0] = f2tf32(p1);
            pk[(col + 0) * PKS + row1] = f2tf32(p2);
            pk[(col + 1) * PKS + row1] = f2tf32(p3);
        }
        sum0 += __shfl_xor_sync(0xffffffffu, sum0, 1);
        sum0 += __shfl_xor_sync(0xffffffffu, sum0, 2);
        sum1 += __shfl_xor_sync(0xffffffffu, sum1, 1);
        sum1 += __shfl_xor_sync(0xffffffffu, sum1, 2);
        rl0 = rl0 * al0 + sum0;
        rl1 = rl1 * al1 + sum1;

        #pragma unroll
        for (int nt = 0; nt < 8; nt++) {
            o_acc[nt][0] *= al0; o_acc[nt][1] *= al0;
            o_acc[nt][2] *= al1; o_acc[nt][3] *= al1;
        }
        __syncwarp();   // P stores visible within warp (each warp reads own rows)

        // ---- O += P V ----
        #pragma unroll
        for (int ks = 0; ks < 8; ks++) {
            int kb = ks * 8 + t4;
            int gm = 16 * w + g;
            uint32_t af0 = pk[kb * PKS + gm];
            uint32_t af1 = pk[kb * PKS + gm + 8];
            uint32_t af2 = pk[(kb + 4) * PKS + gm];
            uint32_t af3 = pk[(kb + 4) * PKS + gm + 8];
            uint32_t bf[8][2];
            #pragma unroll
            for (int nt = 0; nt < 8; nt++) {
                int gn = nt * 8 + g;
                bf[nt][0] = sv[kb * SVS + gn];
                bf[nt][1] = sv[(kb + 4) * SVS + gn];
            }
            #pragma unroll
            for (int nt = 0; nt < 8; nt++) {
                float* d = o_acc[nt];
                MMA_TF32(d, af0, af1, af2, af3, bf[nt][0], bf[nt][1]);
            }
        }
    }

    // ---- epilogue: O = acc / l ----
    float inv0 = 1.f / rl0;
    float inv1 = 1.f / rl1;
    int row0 = t0 + 16 * w + g;
    int row1 = row0 + 8;
    #pragma unroll
    for (int nt = 0; nt < 8; nt++) {
        int dcol = nt * 8 + 2 * t4;
        float2 v0, v1;
        v0.x = o_acc[nt][0] * inv0; v0.y = o_acc[nt][1] * inv0;
        v1.x = o_acc[nt][2] * inv1; v1.y = o_acc[nt][3] * inv1;
        *(float2*)&O[obase + (size_t)row0 * CDIM + dcol] = v0;
        *(float2*)&O[obase + (size_t)row1 * CDIM + dcol] = v1;
    }
}

// ---------------------------------------------------------------------------
// Launch
// ---------------------------------------------------------------------------
extern "C" void kernel_launch(void* const* d_in, const int* in_sizes, int n_in,
                              void* d_out, int out_size) {
    const float* x     = (const float*)d_in[0];
    const float* Wq    = (const float*)d_in[1];
    const float* Wk    = (const float*)d_in[2];
    const float* Wv    = (const float*)d_in[3];
    const float* Wo    = (const float*)d_in[4];
    const float* bo    = (const float*)d_in[5];
    const float* ln1_g = (const float*)d_in[6];
    const float* ln1_b = (const float*)d_in[7];
    const float* ln2_g = (const float*)d_in[8];
    const float* ln2_b = (const float*)d_in[9];
    const float* W1    = (const float*)d_in[10];
    const float* b1    = (const float*)d_in[11];
    const float* W2    = (const float*)d_in[12];
    const float* b2    = (const float*)d_in[13];
    float* out = (float*)d_out;

    float *xn, *qkv, *att, *x2, *y, *hbuf, *wqkv;
    cudaGetSymbolAddress((void**)&xn,   g_xn);
    cudaGetSymbolAddress((void**)&qkv,  g_qkv);
    cudaGetSymbolAddress((void**)&att,  g_att);
    cudaGetSymbolAddress((void**)&x2,   g_x2);
    cudaGetSymbolAddress((void**)&y,    g_y);
    cudaGetSymbolAddress((void**)&hbuf, g_h);
    cudaGetSymbolAddress((void**)&wqkv, g_wqkv);

    static bool attr_done = false;
    if (!attr_done) {
        cudaFuncSetAttribute(flash_tc_kernel,
                             cudaFuncAttributeMaxDynamicSharedMemorySize,
                             FLASH_SMEM);
        attr_done = true;
    }

    // 1. repack QKV weights into fused [C, 3*H*D]
    repackqkv_kernel<<<(HEADS * CDIM * HD + 255) / 256, 256>>>(Wq, Wk, Wv, wqkv);

    // 2. LN1
    ln_kernel<<<NTOK, 256>>>(x, ln1_g, ln1_b, xn);

    // 3. fused QKV projection: [8192,768] x [768,2304]
    {
        dim3 grid(QKVN / 128, NTOK / 128);
        tgemm_kernel<0,0,0><<<grid, 256>>>(xn, wqkv, nullptr, nullptr, qkv,
                                           NTOK, QKVN, CDIM);
    }

    // 4. tensor-core flash attention (Q/K/V strided views into qkv)
    {
        dim3 grid(TSEQ / 128, BB * HEADS);
        flash_tc_kernel<<<grid, 256, FLASH_SMEM>>>(qkv, qkv + CDIM,
                                                   qkv + 2 * CDIM, att);
    }

    // 5. output projection + bias + residual(x) -> x2
    {
        dim3 grid(CDIM / 128, NTOK / 128);
        tgemm_kernel<0,1,1><<<grid, 256>>>(att, Wo, bo, x, x2, NTOK, CDIM, CDIM);
    }

    // 6. LN2
    ln_kernel<<<NTOK, 256>>>(x2, ln2_g, ln2_b, y);

    // 7. FC1 + bias + GELU
    {
        dim3 grid(MLPD / 128, NTOK / 128);
        tgemm_kernel<1,1,0><<<grid, 256>>>(y, W1, b1, nullptr, hbuf,
                                           NTOK, MLPD, CDIM);
    }

    // 8. FC2 + bias + residual(x2) -> out
    {
        dim3 grid(CDIM / 128, NTOK / 128);
        tgemm_kernel<0,1,1><<<grid, 256>>>(hbuf, W2, b2, x2, out,
                                           NTOK, CDIM, MLPD);
    }
}

// round 9
// speedup vs baseline: 3.4158x; 1.5687x over previous
#include <cuda_runtime.h>
#include <math.h>
#include <stdint.h>

// Problem constants
#define BB    4
#define TSEQ  2048
#define CDIM  768
#define HEADS 12
#define HD    64
#define MLPD  3072
#define NTOK  (BB*TSEQ)          // 8192
#define QKVN  (3*CDIM)           // 2304

// ---------------------------------------------------------------------------
// Scratch (device globals; no allocation allowed)
// ---------------------------------------------------------------------------
__device__ float g_xn  [NTOK*CDIM];
__device__ float g_qkv [NTOK*QKVN];
__device__ float g_att [NTOK*CDIM];
__device__ float g_x2  [NTOK*CDIM];
__device__ float g_y   [NTOK*CDIM];
__device__ float g_h   [NTOK*MLPD];
__device__ float g_wqkv[CDIM*QKVN];

// ---------------------------------------------------------------------------
// Repack [H,C,D] x3 -> fused [C, 3*H*D]
// ---------------------------------------------------------------------------
__global__ void repackqkv_kernel(const float* __restrict__ wq,
                                 const float* __restrict__ wk,
                                 const float* __restrict__ wv,
                                 float* __restrict__ o) {
    int i = blockIdx.x * 256 + threadIdx.x;
    if (i >= HEADS * CDIM * HD) return;
    int h = i / (CDIM * HD);
    int r = i % (CDIM * HD);
    int c = r / HD;
    int d = r % HD;
    size_t base = (size_t)c * QKVN + h * HD + d;
    o[base]            = wq[i];
    o[base + CDIM]     = wk[i];
    o[base + 2*CDIM]   = wv[i];
}

// ---------------------------------------------------------------------------
// LayerNorm: one block per token row, 256 threads, C=768 -> 3 elems/thread
// ---------------------------------------------------------------------------
__global__ void ln_kernel(const float* __restrict__ x,
                          const float* __restrict__ g,
                          const float* __restrict__ b,
                          float* __restrict__ out) {
    int row = blockIdx.x;
    int tid = threadIdx.x;
    const float* xr = x + (size_t)row * CDIM;

    float v0 = xr[tid];
    float v1 = xr[tid + 256];
    float v2 = xr[tid + 512];
    float s  = v0 + v1 + v2;
    float s2 = v0*v0 + v1*v1 + v2*v2;

    #pragma unroll
    for (int o = 16; o > 0; o >>= 1) {
        s  += __shfl_xor_sync(0xffffffffu, s,  o);
        s2 += __shfl_xor_sync(0xffffffffu, s2, o);
    }
    __shared__ float rs[8], rs2[8];
    int w = tid >> 5, l = tid & 31;
    if (l == 0) { rs[w] = s; rs2[w] = s2; }
    __syncthreads();
    if (tid < 32) {
        float a  = (l < 8) ? rs[l]  : 0.f;
        float a2 = (l < 8) ? rs2[l] : 0.f;
        #pragma unroll
        for (int o = 4; o > 0; o >>= 1) {
            a  += __shfl_xor_sync(0xffffffffu, a,  o);
            a2 += __shfl_xor_sync(0xffffffffu, a2, o);
        }
        if (l == 0) { rs[0] = a; rs2[0] = a2; }
    }
    __syncthreads();
    float mu  = rs[0] * (1.f / CDIM);
    float var = rs2[0] * (1.f / CDIM) - mu * mu;
    float inv = rsqrtf(var + 1e-6f);

    float* orow = out + (size_t)row * CDIM;
    orow[tid]       = (v0 - mu) * inv * g[tid]       + b[tid];
    orow[tid + 256] = (v1 - mu) * inv * g[tid + 256] + b[tid + 256];
    orow[tid + 512] = (v2 - mu) * inv * g[tid + 512] + b[tid + 512];
}

// ---------------------------------------------------------------------------
// Common helpers
// ---------------------------------------------------------------------------
__device__ __forceinline__ float gelu_exact(float v) {
    return 0.5f * v * (1.0f + erff(v * 0.70710678118654752f));
}

__device__ __forceinline__ uint32_t f2tf32(float f) {
    uint32_t u;
    asm("cvt.rna.tf32.f32 %0, %1;" : "=r"(u) : "f"(f));
    return u;
}

#define MMA_TF32(d, a0,a1,a2,a3, b0,b1)                                      \
    asm volatile(                                                            \
        "mma.sync.aligned.m16n8k8.row.col.f32.tf32.tf32.f32 "                \
        "{%0,%1,%2,%3}, {%4,%5,%6,%7}, {%8,%9}, {%0,%1,%2,%3};"              \
        : "+f"(d[0]), "+f"(d[1]), "+f"(d[2]), "+f"(d[3])                     \
        : "r"(a0), "r"(a1), "r"(a2), "r"(a3), "r"(b0), "r"(b1))

__device__ __forceinline__ void cp16(float* dst_smem, const float* src_gmem) {
    uint32_t d = (uint32_t)__cvta_generic_to_shared(dst_smem);
    asm volatile("cp.async.cg.shared.global [%0], [%1], 16;\n"
                 :: "r"(d), "l"(src_gmem));
}
#define CP_COMMIT()  asm volatile("cp.async.commit_group;\n" ::: "memory")
#define CP_WAIT(n)   asm volatile("cp.async.wait_group %0;\n" :: "n"(n) : "memory")

// ---------------------------------------------------------------------------
// TF32 tensor-core GEMM v2: 3-stage cp.async pipeline.
// C = act(A[M,K] @ B[K,N] + bias) + res
// 128x128 tile, BK=32, 256 threads (8 warps 2x4), mma.m16n8k8.tf32.
// smem per stage: sA [128 m][36]  (stride 36 -> frag bank 4*gq+t4, bijective)
//                 sB [32 k][136]  (stride 136 -> frag bank 8*t4+gq, bijective)
// cp.async stores hit the conflict-free 4-phase floor on both tiles.
// mma consumes raw f32 bits (HW tf32 truncation) — no cvt in the hot loop.
// ---------------------------------------------------------------------------
#define AST 36
#define BST 136
#define STG_WORDS (128*AST + 32*BST)      // 8960 words = 35840 B
#define NSTAGE 3
#define GEMM_SMEM (NSTAGE*STG_WORDS*4)    // 107520 B

template<int ACT, int HASBIAS, int HASRES>
__global__ void __launch_bounds__(256, 2)
tgemm_kernel(const float* __restrict__ A, const float* __restrict__ B,
             const float* __restrict__ bias, const float* __restrict__ res,
             float* __restrict__ C, int M, int N, int K) {
    extern __shared__ float smg[];

    int tid  = threadIdx.x;
    int lane = tid & 31;
    int warp = tid >> 5;
    int wm = warp >> 2;            // 0..1 -> 64 rows each
    int wn = warp & 3;             // 0..3 -> 32 cols each
    int t4 = lane & 3;
    int gq = lane >> 2;
    int m0 = blockIdx.y * 128, n0 = blockIdx.x * 128;

    // A loader: thread covers row arow, k-half ap (4 x 16B chunks)
    int arow = tid >> 1;
    int ap   = tid & 1;
    const float* Ap = A + (size_t)(m0 + arow) * K + ap * 16;
    // B loader: thread covers k-row brow, col chunks bch + 32c
    int brow = tid >> 3;
    int bch  = (tid & 7) * 4;
    const float* Bp = B + (size_t)brow * N + n0 + bch;

    float acc[4][4][4];
    #pragma unroll
    for (int a = 0; a < 4; a++)
        #pragma unroll
        for (int b = 0; b < 4; b++)
            #pragma unroll
            for (int c = 0; c < 4; c++) acc[a][b][c] = 0.f;

    const int NK = K / 32;

    // prologue: issue stages 0..NSTAGE-2
    #pragma unroll
    for (int s = 0; s < NSTAGE - 1; s++) {
        float* sa = smg + s * STG_WORDS;
        float* sb = sa + 128 * AST;
        int k0 = s * 32;
        #pragma unroll
        for (int c = 0; c < 4; c++)
            cp16(&sa[arow * AST + ap * 16 + c * 4], Ap + k0 + c * 4);
        #pragma unroll
        for (int c = 0; c < 4; c++)
            cp16(&sb[brow * BST + bch + c * 32],
                 Bp + (size_t)k0 * N + c * 32);
        CP_COMMIT();
    }

    for (int i = 0; i < NK; i++) {
        CP_WAIT(NSTAGE - 2);
        __syncthreads();

        const uint32_t* sa = (const uint32_t*)(smg + (i % NSTAGE) * STG_WORDS);
        const uint32_t* sb = sa + 128 * AST;

        #pragma unroll
        for (int ks = 0; ks < 4; ks++) {
            int kb = ks * 8 + t4;
            uint32_t bf[4][2];
            #pragma unroll
            for (int nt = 0; nt < 4; nt++) {
                int gn = wn * 32 + nt * 8 + gq;
                bf[nt][0] = sb[kb * BST + gn];
                bf[nt][1] = sb[(kb + 4) * BST + gn];
            }
            uint32_t af[4][4];
            #pragma unroll
            for (int mt = 0; mt < 4; mt++) {
                int gm = wm * 64 + mt * 16 + gq;
                af[mt][0] = sa[gm * AST + kb];           // A[g][t4]
                af[mt][1] = sa[(gm + 8) * AST + kb];     // A[g+8][t4]
                af[mt][2] = sa[gm * AST + kb + 4];       // A[g][t4+4]
                af[mt][3] = sa[(gm + 8) * AST + kb + 4]; // A[g+8][t4+4]
            }
            #pragma unroll
            for (int mt = 0; mt < 4; mt++)
                #pragma unroll
                for (int nt = 0; nt < 4; nt++) {
                    float* d = acc[mt][nt];
                    MMA_TF32(d, af[mt][0], af[mt][1], af[mt][2], af[mt][3],
                             bf[nt][0], bf[nt][1]);
                }
        }

        // issue tile i+NSTAGE-1 (or empty group to keep wait counts valid)
        int nt_ = i + NSTAGE - 1;
        if (nt_ < NK) {
            float* sa_w = smg + (nt_ % NSTAGE) * STG_WORDS;
            float* sb_w = sa_w + 128 * AST;
            int k0 = nt_ * 32;
            #pragma unroll
            for (int c = 0; c < 4; c++)
                cp16(&sa_w[arow * AST + ap * 16 + c * 4], Ap + k0 + c * 4);
            #pragma unroll
            for (int c = 0; c < 4; c++)
                cp16(&sb_w[brow * BST + bch + c * 32],
                     Bp + (size_t)k0 * N + c * 32);
        }
        CP_COMMIT();
    }

    // Epilogue
    #pragma unroll
    for (int mt = 0; mt < 4; mt++) {
        int gr = m0 + wm * 64 + mt * 16 + gq;
        #pragma unroll
        for (int nt = 0; nt < 4; nt++) {
            int gc = n0 + wn * 32 + nt * 8 + t4 * 2;
            float2 v0, v1;
            v0.x = acc[mt][nt][0]; v0.y = acc[mt][nt][1];
            v1.x = acc[mt][nt][2]; v1.y = acc[mt][nt][3];
            if (HASBIAS) {
                float2 bb = *(const float2*)&bias[gc];
                v0.x += bb.x; v0.y += bb.y;
                v1.x += bb.x; v1.y += bb.y;
            }
            if (ACT == 1) {
                v0.x = gelu_exact(v0.x); v0.y = gelu_exact(v0.y);
                v1.x = gelu_exact(v1.x); v1.y = gelu_exact(v1.y);
            }
            if (HASRES) {
                float2 r0 = *(const float2*)&res[(size_t)gr * N + gc];
                float2 r1 = *(const float2*)&res[(size_t)(gr + 8) * N + gc];
                v0.x += r0.x; v0.y += r0.y;
                v1.x += r1.x; v1.y += r1.y;
            }
            *(float2*)&C[(size_t)gr * N + gc]       = v0;
            *(float2*)&C[(size_t)(gr + 8) * N + gc] = v1;
        }
    }
}

// ---------------------------------------------------------------------------
// Tensor-core flash attention v3: register-prefetched K/V tiles.
// Per (b,h): BR=128 query rows / block (8 warps x 16 rows), BC=64 kv tile.
// Dynamic smem (53.2KB): pk[64][136] (Q^T / K^T / P), sv[64][72] (V).
// ---------------------------------------------------------------------------
#define PKS 136
#define SVS 72
#define FLASH_SMEM ((64*PKS + 64*SVS) * 4)

__global__ void __launch_bounds__(256, 1)
flash_tc_kernel(const float* __restrict__ Q, const float* __restrict__ K,
                const float* __restrict__ V, float* __restrict__ O) {
    extern __shared__ uint32_t smf[];
    uint32_t* pk = smf;              // 64 * PKS
    uint32_t* sv = smf + 64 * PKS;   // 64 * SVS

    int tid  = threadIdx.x;
    int lane = tid & 31;
    int w    = tid >> 5;
    int g    = lane >> 2;
    int t4   = lane & 3;

    int bh = blockIdx.y;
    int b = bh / HEADS, h = bh % HEADS;
    int t0 = blockIdx.x * 128;
    size_t base  = (size_t)b * TSEQ * QKVN + (size_t)h * HD;
    size_t obase = (size_t)b * TSEQ * CDIM + (size_t)h * HD;

    const float scale = 0.03608439182435161f;   // 768^-0.5

    int krow = tid & 63;
    int kdq0 = (tid >> 6) * 4;
    int vdv  = (tid & 15) * 4;

    // ---- stage Q^T (pre-scaled) into pk ----
    #pragma unroll
    for (int it = 0; it < 8; it++) {
        int idx = tid + 256 * it;
        int r  = idx & 127;
        int dq = (idx >> 7) * 4;
        float4 qv = *(const float4*)&Q[base + (size_t)(t0 + r) * QKVN + dq];
        pk[(dq + 0) * PKS + r] = f2tf32(qv.x * scale);
        pk[(dq + 1) * PKS + r] = f2tf32(qv.y * scale);
        pk[(dq + 2) * PKS + r] = f2tf32(qv.z * scale);
        pk[(dq + 3) * PKS + r] = f2tf32(qv.w * scale);
    }

    // preload tile 0 of K/V into registers
    float4 kreg[4], vreg[4];
    #pragma unroll
    for (int it = 0; it < 4; it++) {
        kreg[it] = *(const float4*)&K[base + (size_t)krow * QKVN + kdq0 + 16 * it];
        vreg[it] = *(const float4*)&V[base + (size_t)(tid >> 4) * QKVN +
                                      (size_t)(16 * it) * QKVN + vdv];
    }

    __syncthreads();

    uint32_t qf[8][4];
    #pragma unroll
    for (int ks = 0; ks < 8; ks++) {
        int kb = ks * 8 + t4;
        int gm = 16 * w + g;
        qf[ks][0] = pk[kb * PKS + gm];
        qf[ks][1] = pk[kb * PKS + gm + 8];
        qf[ks][2] = pk[(kb + 4) * PKS + gm];
        qf[ks][3] = pk[(kb + 4) * PKS + gm + 8];
    }

    float o_acc[8][4];
    #pragma unroll
    for (int nt = 0; nt < 8; nt++)
        #pragma unroll
        for (int c = 0; c < 4; c++) o_acc[nt][c] = 0.f;
    float rm0 = -1e30f, rm1 = -1e30f, rl0 = 0.f, rl1 = 0.f;

    const int NKT = TSEQ / 64;
    for (int kt = 0; kt < NKT; kt++) {
        __syncthreads();

        #pragma unroll
        for (int it = 0; it < 4; it++) {
            int dq = kdq0 + 16 * it;
            pk[(dq + 0) * PKS + krow] = f2tf32(kreg[it].x);
            pk[(dq + 1) * PKS + krow] = f2tf32(kreg[it].y);
            pk[(dq + 2) * PKS + krow] = f2tf32(kreg[it].z);
            pk[(dq + 3) * PKS + krow] = f2tf32(kreg[it].w);
        }
        #pragma unroll
        for (int it = 0; it < 4; it++) {
            int r = (tid >> 4) + 16 * it;
            sv[r * SVS + vdv + 0] = f2tf32(vreg[it].x);
            sv[r * SVS + vdv + 1] = f2tf32(vreg[it].y);
            sv[r * SVS + vdv + 2] = f2tf32(vreg[it].z);
            sv[r * SVS + vdv + 3] = f2tf32(vreg[it].w);
        }
        __syncthreads();

        if (kt + 1 < NKT) {
            size_t snext = (size_t)(kt + 1) * 64;
            #pragma unroll
            for (int it = 0; it < 4; it++) {
                kreg[it] = *(const float4*)&K[base + (snext + krow) * QKVN +
                                              kdq0 + 16 * it];
                vreg[it] = *(const float4*)&V[base + (snext + (tid >> 4) +
                                              16 * it) * QKVN + vdv];
            }
        }

        // ---- S = Q K^T ----
        float sacc[8][4];
        #pragma unroll
        for (int nt = 0; nt < 8; nt++)
            #pragma unroll
            for (int c = 0; c < 4; c++) sacc[nt][c] = 0.f;

        #pragma unroll
        for (int ks = 0; ks < 8; ks++) {
            int kb = ks * 8 + t4;
            uint32_t bf[8][2];
            #pragma unroll
            for (int nt = 0; nt < 8; nt++) {
                int gn = nt * 8 + g;
                bf[nt][0] = pk[kb * PKS + gn];
                bf[nt][1] = pk[(kb + 4) * PKS + gn];
            }
            #pragma unroll
            for (int nt = 0; nt < 8; nt++) {
                float* d = sacc[nt];
                MMA_TF32(d, qf[ks][0], qf[ks][1], qf[ks][2], qf[ks][3],
                         bf[nt][0], bf[nt][1]);
            }
        }
        __syncthreads();

        // ---- online softmax ----
        float mx0 = -1e30f, mx1 = -1e30f;
        #pragma unroll
        for (int nt = 0; nt < 8; nt++) {
            mx0 = fmaxf(mx0, fmaxf(sacc[nt][0], sacc[nt][1]));
            mx1 = fmaxf(mx1, fmaxf(sacc[nt][2], sacc[nt][3]));
        }
        mx0 = fmaxf(mx0, __shfl_xor_sync(0xffffffffu, mx0, 1));
        mx0 = fmaxf(mx0, __shfl_xor_sync(0xffffffffu, mx0, 2));
        mx1 = fmaxf(mx1, __shfl_xor_sync(0xffffffffu, mx1, 1));
        mx1 = fmaxf(mx1, __shfl_xor_sync(0xffffffffu, mx1, 2));

        float mn0 = fmaxf(rm0, mx0);
        float mn1 = fmaxf(rm1, mx1);
        float al0 = __expf(rm0 - mn0);
        float al1 = __expf(rm1 - mn1);
        rm0 = mn0; rm1 = mn1;

        int row0 = 16 * w + g;
        int row1 = row0 + 8;
        float sum0 = 0.f, sum1 = 0.f;
        #pragma unroll
        for (int nt = 0; nt < 8; nt++) {
            int col = nt * 8 + 2 * t4;
            float p0 = __expf(sacc[nt][0] - mn0);
            float p1 = __expf(sacc[nt][1] - mn0);
            float p2 = __expf(sacc[nt][2] - mn1);
            float p3 = __expf(sacc[nt][3] - mn1);
            sum0 += p0 + p1;
            sum1 += p2 + p3;
            pk[(col + 0) * PKS + row0] = f2tf32(p0);
            pk[(col + 1) * PKS + row0] = f2tf32(p1);
            pk[(col + 0) * PKS + row1] = f2tf32(p2);
            pk[(col + 1) * PKS + row1] = f2tf32(p3);
        }
        sum0 += __shfl_xor_sync(0xffffffffu, sum0, 1);
        sum0 += __shfl_xor_sync(0xffffffffu, sum0, 2);
        sum1 += __shfl_xor_sync(0xffffffffu, sum1, 1);
        sum1 += __shfl_xor_sync(0xffffffffu, sum1, 2);
        rl0 = rl0 * al0 + sum0;
        rl1 = rl1 * al1 + sum1;

        #pragma unroll
        for (int nt = 0; nt < 8; nt++) {
            o_acc[nt][0] *= al0; o_acc[nt][1] *= al0;
            o_acc[nt][2] *= al1; o_acc[nt][3] *= al1;
        }
        __syncwarp();

        // ---- O += P V ----
        #pragma unroll
        for (int ks = 0; ks < 8; ks++) {
            int kb = ks * 8 + t4;
            int gm = 16 * w + g;
            uint32_t af0 = pk[kb * PKS + gm];
            uint32_t af1 = pk[kb * PKS + gm + 8];
            uint32_t af2 = pk[(kb + 4) * PKS + gm];
            uint32_t af3 = pk[(kb + 4) * PKS + gm + 8];
            uint32_t bf[8][2];
            #pragma unroll
            for (int nt = 0; nt < 8; nt++) {
                int gn = nt * 8 + g;
                bf[nt][0] = sv[kb * SVS + gn];
                bf[nt][1] = sv[(kb + 4) * SVS + gn];
            }
            #pragma unroll
            for (int nt = 0; nt < 8; nt++) {
                float* d = o_acc[nt];
                MMA_TF32(d, af0, af1, af2, af3, bf[nt][0], bf[nt][1]);
            }
        }
    }

    // ---- epilogue: O = acc / l ----
    float inv0 = 1.f / rl0;
    float inv1 = 1.f / rl1;
    int row0 = t0 + 16 * w + g;
    int row1 = row0 + 8;
    #pragma unroll
    for (int nt = 0; nt < 8; nt++) {
        int dcol = nt * 8 + 2 * t4;
        float2 v0, v1;
        v0.x = o_acc[nt][0] * inv0; v0.y = o_acc[nt][1] * inv0;
        v1.x = o_acc[nt][2] * inv1; v1.y = o_acc[nt][3] * inv1;
        *(float2*)&O[obase + (size_t)row0 * CDIM + dcol] = v0;
        *(float2*)&O[obase + (size_t)row1 * CDIM + dcol] = v1;
    }
}

// ---------------------------------------------------------------------------
// Launch
// ---------------------------------------------------------------------------
extern "C" void kernel_launch(void* const* d_in, const int* in_sizes, int n_in,
                              void* d_out, int out_size) {
    const float* x     = (const float*)d_in[0];
    const float* Wq    = (const float*)d_in[1];
    const float* Wk    = (const float*)d_in[2];
    const float* Wv    = (const float*)d_in[3];
    const float* Wo    = (const float*)d_in[4];
    const float* bo    = (const float*)d_in[5];
    const float* ln1_g = (const float*)d_in[6];
    const float* ln1_b = (const float*)d_in[7];
    const float* ln2_g = (const float*)d_in[8];
    const float* ln2_b = (const float*)d_in[9];
    const float* W1    = (const float*)d_in[10];
    const float* b1    = (const float*)d_in[11];
    const float* W2    = (const float*)d_in[12];
    const float* b2    = (const float*)d_in[13];
    float* out = (float*)d_out;

    float *xn, *qkv, *att, *x2, *y, *hbuf, *wqkv;
    cudaGetSymbolAddress((void**)&xn,   g_xn);
    cudaGetSymbolAddress((void**)&qkv,  g_qkv);
    cudaGetSymbolAddress((void**)&att,  g_att);
    cudaGetSymbolAddress((void**)&x2,   g_x2);
    cudaGetSymbolAddress((void**)&y,    g_y);
    cudaGetSymbolAddress((void**)&hbuf, g_h);
    cudaGetSymbolAddress((void**)&wqkv, g_wqkv);

    static bool attr_done = false;
    if (!attr_done) {
        cudaFuncSetAttribute(flash_tc_kernel,
                             cudaFuncAttributeMaxDynamicSharedMemorySize,
                             FLASH_SMEM);
        cudaFuncSetAttribute(tgemm_kernel<0,0,0>,
                             cudaFuncAttributeMaxDynamicSharedMemorySize,
                             GEMM_SMEM);
        cudaFuncSetAttribute(tgemm_kernel<0,1,1>,
                             cudaFuncAttributeMaxDynamicSharedMemorySize,
                             GEMM_SMEM);
        cudaFuncSetAttribute(tgemm_kernel<1,1,0>,
                             cudaFuncAttributeMaxDynamicSharedMemorySize,
                             GEMM_SMEM);
        attr_done = true;
    }

    // 1. repack QKV weights into fused [C, 3*H*D]
    repackqkv_kernel<<<(HEADS * CDIM * HD + 255) / 256, 256>>>(Wq, Wk, Wv, wqkv);

    // 2. LN1
    ln_kernel<<<NTOK, 256>>>(x, ln1_g, ln1_b, xn);

    // 3. fused QKV projection: [8192,768] x [768,2304]
    {
        dim3 grid(QKVN / 128, NTOK / 128);
        tgemm_kernel<0,0,0><<<grid, 256, GEMM_SMEM>>>(xn, wqkv, nullptr, nullptr,
                                                      qkv, NTOK, QKVN, CDIM);
    }

    // 4. tensor-core flash attention (Q/K/V strided views into qkv)
    {
        dim3 grid(TSEQ / 128, BB * HEADS);
        flash_tc_kernel<<<grid, 256, FLASH_SMEM>>>(qkv, qkv + CDIM,
                                                   qkv + 2 * CDIM, att);
    }

    // 5. output projection + bias + residual(x) -> x2
    {
        dim3 grid(CDIM / 128, NTOK / 128);
        tgemm_kernel<0,1,1><<<grid, 256, GEMM_SMEM>>>(att, Wo, bo, x, x2,
                                                      NTOK, CDIM, CDIM);
    }

    // 6. LN2
    ln_kernel<<<NTOK, 256>>>(x2, ln2_g, ln2_b, y);

    // 7. FC1 + bias + GELU
    {
        dim3 grid(MLPD / 128, NTOK / 128);
        tgemm_kernel<1,1,0><<<grid, 256, GEMM_SMEM>>>(y, W1, b1, nullptr, hbuf,
                                                      NTOK, MLPD, CDIM);
    }

    // 8. FC2 + bias + residual(x2) -> out
    {
        dim3 grid(CDIM / 128, NTOK / 128);
        tgemm_kernel<0,1,1><<<grid, 256, GEMM_SMEM>>>(hbuf, W2, b2, x2, out,
                                                      NTOK, CDIM, MLPD);
    }
}